// round 10
// baseline (speedup 1.0000x reference)
#include <cuda_runtime.h>
#include <cuda_fp16.h>
#include <math.h>
#include <stdint.h>

// Problem constants
#define NN 30000       // node_size
#define RR 1000        // rel_size
#define TT 200000      // triple_size
#define DD 128         // DIM
#define BB 2048        // BATCH
#define OD 768         // output feature dim (6 * 128)
#define NJ 30080       // padded column count for dot matrix (235*128)
#define MR 4096        // stacked query rows (l 0..2047, r 2048..4095)
#define GAMMA_C 3.0f
#define LAMB_C 30.0f
#define TAU_C 10.0f
#define KCH 12         // 768 / 64 K-chunks in GEMM

// ---------------- scratch (device globals; no allocation allowed) ----------------
__device__ float g_tri[(size_t)TT * DD];
__device__ float g_att[4 * TT];              // exp(logit) per edge: [e0, e1, r0, r1]
__device__ float g_acc[(size_t)NN * DD];
__device__ float g_den[6 * NN];              // [cnt_ent, cnt_rel, z0, z1, z2, z3]
__device__ float g_feats[(size_t)NN * DD];
__device__ float g_out[(size_t)NN * OD];
__device__ float g_embsq[NN];
__device__ float g_asq[MR];
__device__ float g_pos[BB];
__device__ float g_dot[(size_t)MR * NJ];
__device__ float g_lse[MR];
// fp16 split operands: A = Ahi + Alo (exact to 2^-22), B = Bh (single round)
__device__ __align__(16) __half g_Ahi[(size_t)MR * OD];
__device__ __align__(16) __half g_Alo[(size_t)MR * OD];
__device__ __align__(16) __half g_Bh[(size_t)NJ * OD];

// ---------------- helpers ----------------
__device__ __forceinline__ float warp_sum_f(float v) {
#pragma unroll
    for (int o = 16; o; o >>= 1) v += __shfl_xor_sync(0xffffffffu, v, o);
    return v;
}
__device__ __forceinline__ uint32_t smem_u32(const void* p) {
    uint32_t a;
    asm("{ .reg .u64 t; cvta.to.shared.u64 t, %1; cvt.u32.u64 %0, t; }" : "=r"(a) : "l"(p));
    return a;
}
__device__ __forceinline__ uint32_t swz128(uint32_t b) { return b ^ ((b >> 3) & 0x70); }

__device__ __forceinline__ void cp16(uint32_t dst, const void* src) {
    asm volatile("cp.async.cg.shared.global [%0], [%1], 16;" :: "r"(dst), "l"(src));
}
#define CP_COMMIT() asm volatile("cp.async.commit_group;" ::: "memory")
#define CP_WAIT(n)  asm volatile("cp.async.wait_group %0;" :: "n"(n) : "memory")

__device__ __forceinline__ void ldsm4(uint32_t* r, uint32_t addr) {
    asm volatile("ldmatrix.sync.aligned.m8n8.x4.shared.b16 {%0,%1,%2,%3}, [%4];"
                 : "=r"(r[0]), "=r"(r[1]), "=r"(r[2]), "=r"(r[3]) : "r"(addr));
}
// fp32-accum fp16 mma (hi product)
__device__ __forceinline__ void mma_f16(float* c, const uint32_t* a, uint32_t b0, uint32_t b1) {
    asm volatile(
        "mma.sync.aligned.m16n8k16.row.col.f32.f16.f16.f32 "
        "{%0,%1,%2,%3}, {%4,%5,%6,%7}, {%8,%9}, {%0,%1,%2,%3};"
        : "+f"(c[0]), "+f"(c[1]), "+f"(c[2]), "+f"(c[3])
        : "r"(a[0]), "r"(a[1]), "r"(a[2]), "r"(a[3]), "r"(b0), "r"(b1));
}
// fp16-accum fp16 mma (lo product; |sum| << 1, error ~1e-4 abs, 2x rate)
__device__ __forceinline__ void mma_f16acc(uint32_t* c, const uint32_t* a, uint32_t b0, uint32_t b1) {
    asm volatile(
        "mma.sync.aligned.m16n8k16.row.col.f16.f16.f16.f16 "
        "{%0,%1}, {%2,%3,%4,%5}, {%6,%7}, {%0,%1};"
        : "+r"(c[0]), "+r"(c[1])
        : "r"(a[0]), "r"(a[1]), "r"(a[2]), "r"(a[3]), "r"(b0), "r"(b1));
}
// vectorized global float4 add-reduction
__device__ __forceinline__ void red4(float* dst, float x, float y, float z, float w) {
    asm volatile("red.global.add.v4.f32 [%0], {%1, %2, %3, %4};"
                 :: "l"(dst), "f"(x), "f"(y), "f"(z), "f"(w) : "memory");
}

// ---------------- zero acc + denominators ----------------
__global__ void k_zero() {
    size_t i = (size_t)blockIdx.x * blockDim.x + threadIdx.x;
    if (i < (size_t)NN * DD) g_acc[i] = 0.0f;
    if (i < 6 * NN) g_den[i] = 0.0f;
}

// ---------------- tri_rel direct (r_index[0] == arange) + exp(att logits) ----------------
__global__ void k_tri_direct(const int* __restrict__ r1, const float* __restrict__ rval,
                             const float* __restrict__ rel_emb,
                             const float* __restrict__ attn_e, const float* __restrict__ attn_r) {
    int warp = (int)(((size_t)blockIdx.x * blockDim.x + threadIdx.x) >> 5);
    int lane = threadIdx.x & 31;
    if (warp >= TT) return;
    int rel = r1[warp];
    float v = rval[warp];
    float4 a = ((const float4*)(rel_emb + (size_t)rel * DD))[lane];
    a.x *= v; a.y *= v; a.z *= v; a.w *= v;
    float ss = a.x * a.x + a.y * a.y + a.z * a.z + a.w * a.w;
    ss = warp_sum_f(ss);
    float inv = 1.0f / fmaxf(sqrtf(ss), 1e-12f);
    a.x *= inv; a.y *= inv; a.z *= inv; a.w *= inv;
    ((float4*)(g_tri + (size_t)warp * DD))[lane] = a;

    float4 k0 = ((const float4*)attn_e)[lane];
    float4 k1 = ((const float4*)(attn_e + DD))[lane];
    float4 k2 = ((const float4*)attn_r)[lane];
    float4 k3 = ((const float4*)(attn_r + DD))[lane];
    float d0 = a.x * k0.x + a.y * k0.y + a.z * k0.z + a.w * k0.w;
    float d1 = a.x * k1.x + a.y * k1.y + a.z * k1.z + a.w * k1.w;
    float d2 = a.x * k2.x + a.y * k2.y + a.z * k2.z + a.w * k2.w;
    float d3 = a.x * k3.x + a.y * k3.y + a.z * k3.z + a.w * k3.w;
    d0 = warp_sum_f(d0);
    d1 = warp_sum_f(d1);
    d2 = warp_sum_f(d2);
    d3 = warp_sum_f(d3);
    if (lane == 0) {
        g_att[0 * TT + warp] = expf(d0);
        g_att[1 * TT + warp] = expf(d1);
        g_att[2 * TT + warp] = expf(d2);
        g_att[3 * TT + warp] = expf(d3);
    }
}

// ---------------- all 6 denominators upfront (counts + 4 softmax z) ----------------
__global__ void k_denoms(const int* __restrict__ ent_rows, const int* __restrict__ rel_rows,
                         const int* __restrict__ adj_rows) {
    int e = blockIdx.x * blockDim.x + threadIdx.x;
    if (e >= TT) return;
    atomicAdd(&g_den[ent_rows[e]], 1.0f);
    atomicAdd(&g_den[NN + rel_rows[e]], 1.0f);
    int r = adj_rows[e];
#pragma unroll
    for (int l = 0; l < 4; l++)
        atomicAdd(&g_den[(2 + l) * NN + r], g_att[l * TT + e]);
}

// ---------------- sparse_mean scatter (vector red) ----------------
__global__ void k_scatter_mean(const int* __restrict__ adj, const float* __restrict__ emb) {
    int warp = (int)(((size_t)blockIdx.x * blockDim.x + threadIdx.x) >> 5);
    int lane = threadIdx.x & 31;
    if (warp >= TT) return;
    int row = adj[warp];
    int col = adj[TT + warp];
    float4 a = ((const float4*)(emb + (size_t)col * DD))[lane];
    red4(g_acc + (size_t)row * DD + lane * 4, a.x, a.y, a.z, a.w);
}

// finalize mean; zeroes g_acc; writes g_out fp32 + g_Bh fp16
__global__ void k_finalize_mean(int colofs, int cntsel) {
    size_t idx = (size_t)blockIdx.x * blockDim.x + threadIdx.x;
    if (idx >= (size_t)NN * DD) return;
    int n = (int)(idx / DD);
    int d = (int)(idx % DD);
    float c = fmaxf(g_den[cntsel * NN + n], 1.0f);
    float f = tanhf(g_acc[idx] / c);
    g_acc[idx] = 0.0f;
    g_feats[idx] = f;
    size_t o = (size_t)n * OD + colofs + d;
    g_out[o] = f;
    g_Bh[o] = __float2half_rn(f);
}

// ---------------- GAT reflected-neighbor weighted scatter (vector red) ----------------
__global__ void k_reflect(const int* __restrict__ adj, int lidx) {
    int warp = (int)(((size_t)blockIdx.x * blockDim.x + threadIdx.x) >> 5);
    int lane = threadIdx.x & 31;
    if (warp >= TT) return;
    int row = adj[warp];
    int col = adj[TT + warp];
    float w = g_att[lidx * TT + warp] / g_den[(2 + lidx) * NN + row];
    float4 t = ((const float4*)(g_tri + (size_t)warp * DD))[lane];
    float4 nb = ((const float4*)(g_feats + (size_t)col * DD))[lane];
    float s = nb.x * t.x + nb.y * t.y + nb.z * t.z + nb.w * t.w;
    s = warp_sum_f(s);
    float c2 = 2.0f * s;
    red4(g_acc + (size_t)row * DD + lane * 4,
         w * (nb.x - c2 * t.x), w * (nb.y - c2 * t.y),
         w * (nb.z - c2 * t.z), w * (nb.w - c2 * t.w));
}

// finalize tanh; zeroes g_acc; writes g_out fp32 + g_Bh fp16
__global__ void k_finalize_tanh(int colofs) {
    size_t idx = (size_t)blockIdx.x * blockDim.x + threadIdx.x;
    if (idx >= (size_t)NN * DD) return;
    int n = (int)(idx / DD);
    int d = (int)(idx % DD);
    float f = tanhf(g_acc[idx]);
    g_acc[idx] = 0.0f;
    g_feats[idx] = f;
    size_t o = (size_t)n * OD + colofs + d;
    g_out[o] = f;
    g_Bh[o] = __float2half_rn(f);
}

// ---------------- row squared norms + zero pad rows of Bh ----------------
__global__ void k_embsq() {
    int row = (int)(((size_t)blockIdx.x * blockDim.x + threadIdx.x) >> 5);
    int lane = threadIdx.x & 31;
    if (row >= NJ) return;
    if (row < NN) {
        const float4* p = (const float4*)(g_out + (size_t)row * OD);
        float ss = 0.0f;
#pragma unroll
        for (int j = lane; j < OD / 4; j += 32) {
            float4 a = p[j];
            ss += a.x * a.x + a.y * a.y + a.z * a.z + a.w * a.w;
        }
        ss = warp_sum_f(ss);
        if (lane == 0) g_embsq[row] = ss;
    } else {
        size_t o = (size_t)row * OD;
        for (int j = lane * 4; j < OD; j += 128) {
#pragma unroll
            for (int q = 0; q < 4; q++) g_Bh[o + j + q] = __float2half_rn(0.0f);
        }
    }
}

// ---------------- gather A (fp16 hi/lo split) + pos + asq ----------------
__global__ void k_pairprep(const int* __restrict__ pairs) {
    int i = blockIdx.x;
    int li = pairs[2 * i];
    int ri = pairs[2 * i + 1];
    const float* L = g_out + (size_t)li * OD;
    const float* R = g_out + (size_t)ri * OD;
    float part = 0.0f;
    for (int c = threadIdx.x; c < OD; c += 256) {
        float a = L[c];
        float b = R[c];
        __half ha = __float2half_rn(a);
        __half hb = __float2half_rn(b);
        size_t oa = (size_t)i * OD + c;
        size_t ob = (size_t)(i + BB) * OD + c;
        g_Ahi[oa] = ha;
        g_Alo[oa] = __float2half_rn(a - __half2float(ha));
        g_Ahi[ob] = hb;
        g_Alo[ob] = __float2half_rn(b - __half2float(hb));
        float d = a - b;
        part += d * d;
    }
    __shared__ float sh[8];
    int lane = threadIdx.x & 31, wid = threadIdx.x >> 5;
    part = warp_sum_f(part);
    if (lane == 0) sh[wid] = part;
    __syncthreads();
    if (threadIdx.x == 0) {
        float s = 0.0f;
        for (int w = 0; w < 8; w++) s += sh[w];
        g_pos[i] = s;
        g_asq[i] = g_embsq[li];
        g_asq[i + BB] = g_embsq[ri];
    }
}

// ---------------- mma.sync fp16x2 GEMM: g_dot = A @ B^T ----------------
// hi product fp32-accum, lo product fp16-accum (2x rate). 3-stage cp.async.
__global__ __launch_bounds__(256, 1) void k_gemm_tc() {
    extern __shared__ char smraw[];
    uint32_t sm0 = smem_u32(smraw);
    uint32_t smbase = (sm0 + 1023u) & ~1023u;

    const int tid = threadIdx.x;
    const int warp = tid >> 5;
    const int lane = tid & 31;
    const int bi = blockIdx.x;   // M tile (0..31)
    const int bj = blockIdx.y;   // N tile (0..234)

    const uint4* srcs[3];
    srcs[0] = (const uint4*)g_Ahi + (size_t)(bi * 128) * 96;
    srcs[1] = (const uint4*)g_Alo + (size_t)(bi * 128) * 96;
    srcs[2] = (const uint4*)g_Bh + (size_t)(bj * 128) * 96;

    const int frow = tid >> 3;
    const int fc = tid & 7;
#define FILL_STAGE(kc, stage)                                                    \
    do {                                                                         \
        uint32_t st_ = smbase + (uint32_t)(stage) * 49152u;                      \
        _Pragma("unroll")                                                        \
        for (int m_ = 0; m_ < 3; m_++) {                                         \
            const uint4* src_ = srcs[m_];                                        \
            uint32_t tb_ = st_ + m_ * 16384u;                                    \
            _Pragma("unroll")                                                    \
            for (int i_ = 0; i_ < 4; i_++) {                                     \
                int row_ = frow + i_ * 32;                                       \
                cp16(tb_ + swz128((uint32_t)(row_ * 128 + fc * 16)),             \
                     src_ + (size_t)row_ * 96 + (kc) * 8 + fc);                  \
            }                                                                    \
        }                                                                        \
        CP_COMMIT();                                                             \
    } while (0)

    const int wm = warp >> 2;
    const int wn = warp & 3;
    uint32_t mrow[4], brow[2];
#pragma unroll
    for (int mi = 0; mi < 4; mi++)
        mrow[mi] = (uint32_t)((wm * 64 + mi * 16 + (lane & 15)) * 128);
#pragma unroll
    for (int g = 0; g < 2; g++)
        brow[g] = (uint32_t)((wn * 32 + g * 16 + (lane & 7) + ((lane >> 3) & 1) * 8) * 128);
    const uint32_t csel = (uint32_t)(((lane >> 4) & 1) * 16);

    float acc[4][4][4];
    uint32_t accLo[4][4][2];
#pragma unroll
    for (int mi = 0; mi < 4; mi++)
#pragma unroll
        for (int nj = 0; nj < 4; nj++) {
#pragma unroll
            for (int q = 0; q < 4; q++) acc[mi][nj][q] = 0.0f;
            accLo[mi][nj][0] = 0u;
            accLo[mi][nj][1] = 0u;
        }

    FILL_STAGE(0, 0);
    FILL_STAGE(1, 1);

    for (int k = 0; k < KCH; k++) {
        if (k + 1 < KCH) CP_WAIT(1);
        else CP_WAIT(0);
        __syncthreads();
        if (k + 2 < KCH) FILL_STAGE(k + 2, (k + 2) % 3);

        int s = k % 3;
        uint32_t Ahb = smbase + (uint32_t)s * 49152u;
        uint32_t Alb = Ahb + 16384u;
        uint32_t Bhb = Ahb + 32768u;
#pragma unroll
        for (int ks = 0; ks < 4; ks++) {
            uint32_t col = (uint32_t)(ks * 32) + csel;
            uint32_t ahi[4][4], alo[4][4], bh[2][4];
#pragma unroll
            for (int mi = 0; mi < 4; mi++) {
                uint32_t so = swz128(mrow[mi] + col);
                ldsm4(ahi[mi], Ahb + so);
                ldsm4(alo[mi], Alb + so);
            }
#pragma unroll
            for (int g = 0; g < 2; g++) {
                uint32_t so = swz128(brow[g] + col);
                ldsm4(bh[g], Bhb + so);
            }
#pragma unroll
            for (int mi = 0; mi < 4; mi++) {
#pragma unroll
                for (int nj = 0; nj < 4; nj++) {
                    int g = nj >> 1, h = nj & 1;
                    mma_f16(acc[mi][nj], ahi[mi], bh[g][h], bh[g][h + 2]);
                    mma_f16acc(accLo[mi][nj], alo[mi], bh[g][h], bh[g][h + 2]);
                }
            }
        }
    }

    const int mrow0 = bi * 128 + wm * 64;
    const int ncol0 = bj * 128 + wn * 32;
    const int rofs = lane >> 2;
    const int cofs = (lane & 3) * 2;
#pragma unroll
    for (int mi = 0; mi < 4; mi++) {
#pragma unroll
        for (int nj = 0; nj < 4; nj++) {
            size_t r0 = (size_t)(mrow0 + mi * 16 + rofs);
            size_t c0 = (size_t)(ncol0 + nj * 8 + cofs);
            float2 lo0 = __half22float2(*(const __half2*)&accLo[mi][nj][0]);
            float2 lo1 = __half22float2(*(const __half2*)&accLo[mi][nj][1]);
            float2 v0 = make_float2(acc[mi][nj][0] + lo0.x, acc[mi][nj][1] + lo0.y);
            float2 v1 = make_float2(acc[mi][nj][2] + lo1.x, acc[mi][nj][3] + lo1.y);
            *(float2*)(g_dot + r0 * NJ + c0) = v0;
            *(float2*)(g_dot + (r0 + 8) * NJ + c0) = v1;
        }
    }
#undef FILL_STAGE
}

// ---------------- fused loss pass: stats + logsumexp, row cached in SMEM ----------------
__global__ __launch_bounds__(512) void k_pass(const int* __restrict__ pairs) {
    extern __shared__ float srow[];   // NN floats
    const int i = blockIdx.x;
    const int p = i & (BB - 1);
    const int li = pairs[2 * p];
    const int ri = pairs[2 * p + 1];
    const float posg = g_pos[p] + GAMMA_C;
    const float asq = g_asq[i];
    const float* drow = g_dot + (size_t)i * NJ;

    double s = 0.0, s2 = 0.0;
    float mx = -3.4e38f;
    for (int j = threadIdx.x; j < NN; j += 512) {
        float neg = asq + g_embsq[j] - 2.0f * drow[j];
        float lv = posg - neg;
        float fac = 1.0f - (float)(j == li) - (float)(j == ri);
        lv *= fac;
        srow[j] = lv;
        s += lv;
        s2 += (double)lv * (double)lv;
        mx = fmaxf(mx, lv);
    }
    __shared__ double sh_s[16], sh_s2[16];
    __shared__ float sh_m[16];
    __shared__ float bc_mu, bc_sc, bc_Mt;
    int lane = threadIdx.x & 31, wid = threadIdx.x >> 5;
#pragma unroll
    for (int o = 16; o; o >>= 1) {
        s += __shfl_xor_sync(0xffffffffu, s, o);
        s2 += __shfl_xor_sync(0xffffffffu, s2, o);
        mx = fmaxf(mx, __shfl_xor_sync(0xffffffffu, mx, o));
    }
    if (lane == 0) { sh_s[wid] = s; sh_s2[wid] = s2; sh_m[wid] = mx; }
    __syncthreads();
    if (threadIdx.x == 0) {
        double S = 0.0, S2 = 0.0;
        float M = -3.4e38f;
        for (int w = 0; w < 16; w++) { S += sh_s[w]; S2 += sh_s2[w]; M = fmaxf(M, sh_m[w]); }
        double mu = S / (double)NN;
        double var = S2 / (double)NN - mu * mu;
        if (var < 0.0) var = 0.0;
        float sd = (float)fmax(sqrt(var), 1e-30);
        bc_mu = (float)mu;
        bc_sc = LAMB_C / sd;
        bc_Mt = (LAMB_C / sd) * (M - (float)mu);
    }
    __syncthreads();
    const float mu = bc_mu, sc = bc_sc, Mt = bc_Mt;

    double se = 0.0;
    for (int j = threadIdx.x; j < NN; j += 512) {
        float t = sc * (srow[j] - mu) - Mt;
        if (t > -21.0f) se += (double)__expf(t);
    }
#pragma unroll
    for (int o = 16; o; o >>= 1) se += __shfl_xor_sync(0xffffffffu, se, o);
    if (lane == 0) sh_s[wid] = se;
    __syncthreads();
    if (threadIdx.x == 0) {
        double S = 0.0;
        for (int w = 0; w < 16; w++) S += sh_s[w];
        g_lse[i] = (float)((double)Mt + TAU_C + log(S));
    }
}

// ---------------- final mean ----------------
__global__ void k_final(float* __restrict__ out, int out_size) {
    double s = 0.0;
    for (int i = threadIdx.x; i < MR; i += 256) s += (double)g_lse[i];
    __shared__ double sh[8];
    int lane = threadIdx.x & 31, wid = threadIdx.x >> 5;
#pragma unroll
    for (int o = 16; o; o >>= 1) s += __shfl_xor_sync(0xffffffffu, s, o);
    if (lane == 0) sh[wid] = s;
    __syncthreads();
    if (threadIdx.x == 0) {
        double S = 0.0;
        for (int w = 0; w < 8; w++) S += sh[w];
        float val = (float)(S / (double)BB);
        for (int k = 0; k < out_size; k++) out[k] = val;
    }
}

// ---------------- host launch ----------------
extern "C" void kernel_launch(void* const* d_in, const int* in_sizes, int n_in,
                              void* d_out, int out_size) {
    const int* pairs = (const int*)d_in[0];
    const int* ent_adj = (const int*)d_in[1];
    const int* rel_adj = (const int*)d_in[2];
    const int* adj_list = (const int*)d_in[3];
    const int* r_index = (const int*)d_in[4];
    const float* r_val = (const float*)d_in[5];
    const float* ent_emb = (const float*)d_in[7];
    const float* rel_emb = (const float*)d_in[8];
    const float* attn_e = (const float*)d_in[9];
    const float* attn_r = (const float*)d_in[10];
    float* out = (float*)d_out;

    const int NT = 256;
    const int gb_acc = (int)(((size_t)NN * DD + NT - 1) / NT);
    const int gb_ew = (int)(((size_t)TT * 32 + NT - 1) / NT);
    const int gb_et = (TT + NT - 1) / NT;
    const int gb_nw = (int)(((size_t)NJ * 32 + NT - 1) / NT);

    k_tri_direct<<<gb_ew, NT>>>(r_index + TT, r_val, rel_emb, attn_e, attn_r);
    k_zero<<<gb_acc, NT>>>();
    k_denoms<<<gb_et, NT>>>(ent_adj, rel_adj, adj_list);

    // ---- GAT over ent_feature ----
    k_scatter_mean<<<gb_ew, NT>>>(ent_adj, ent_emb);
    k_finalize_mean<<<gb_acc, NT>>>(0, 0);
    for (int l = 0; l < 2; l++) {
        k_reflect<<<gb_ew, NT>>>(adj_list, l);
        k_finalize_tanh<<<gb_acc, NT>>>((l + 1) * DD);
    }

    // ---- GAT over rel_feature ----
    k_scatter_mean<<<gb_ew, NT>>>(rel_adj, rel_emb);
    k_finalize_mean<<<gb_acc, NT>>>(3 * DD, 1);
    for (int l = 0; l < 2; l++) {
        k_reflect<<<gb_ew, NT>>>(adj_list, 2 + l);
        k_finalize_tanh<<<gb_acc, NT>>>((4 + l) * DD);
    }

    // ---- align loss ----
    k_embsq<<<gb_nw, NT>>>();
    k_pairprep<<<BB, NT>>>(pairs);

    const int gemm_smem = 3 * 49152 + 1024;
    cudaFuncSetAttribute(k_gemm_tc, cudaFuncAttributeMaxDynamicSharedMemorySize, gemm_smem);
    dim3 gg(MR / 128, NJ / 128);
    k_gemm_tc<<<gg, 256, gemm_smem>>>();

    const int pass_smem = NN * (int)sizeof(float);
    cudaFuncSetAttribute(k_pass, cudaFuncAttributeMaxDynamicSharedMemorySize, pass_smem);
    k_pass<<<MR, 512, pass_smem>>>(pairs);
    k_final<<<1, 256>>>(out, out_size);
}

// round 11
// speedup vs baseline: 1.7347x; 1.7347x over previous
#include <cuda_runtime.h>
#include <cuda_fp16.h>
#include <math.h>
#include <stdint.h>

// Problem constants
#define NN 30000       // node_size
#define RR 1000        // rel_size
#define TT 200000      // triple_size
#define DD 128         // DIM
#define BB 2048        // BATCH
#define OD 768         // output feature dim (6 * 128)
#define NJ 30080       // padded column count for dot matrix (235*128)
#define MR 4096        // stacked query rows (l 0..2047, r 2048..4095)
#define GAMMA_C 3.0f
#define LAMB_C 30.0f
#define TAU_C 10.0f
#define KCH 12         // 768 / 64 K-chunks in GEMM

// ---------------- scratch (device globals; no allocation allowed) ----------------
__device__ float g_tri[(size_t)TT * DD];
__device__ float g_att[4 * TT];              // exp(logit) per edge: [e0, e1, r0, r1]
__device__ float g_acc[(size_t)NN * DD];
__device__ float g_den[6 * NN];              // [cnt_ent, cnt_rel, z0, z1, z2, z3]
__device__ float g_feats[(size_t)NN * DD];
__device__ float g_out[(size_t)NN * OD];
__device__ float g_embsq[NN];
__device__ float g_asq[MR];
__device__ float g_pos[BB];
__device__ float g_dot[(size_t)MR * NJ];
__device__ float g_lse[MR];
// fp16 operands (single rounding; error budget analyzed in notes)
__device__ __align__(16) __half g_Ah[(size_t)MR * OD];
__device__ __align__(16) __half g_Bh[(size_t)NJ * OD];

// ---------------- helpers ----------------
__device__ __forceinline__ float warp_sum_f(float v) {
#pragma unroll
    for (int o = 16; o; o >>= 1) v += __shfl_xor_sync(0xffffffffu, v, o);
    return v;
}
__device__ __forceinline__ uint32_t smem_u32(const void* p) {
    uint32_t a;
    asm("{ .reg .u64 t; cvta.to.shared.u64 t, %1; cvt.u32.u64 %0, t; }" : "=r"(a) : "l"(p));
    return a;
}
__device__ __forceinline__ uint32_t swz128(uint32_t b) { return b ^ ((b >> 3) & 0x70); }

__device__ __forceinline__ void cp16(uint32_t dst, const void* src) {
    asm volatile("cp.async.cg.shared.global [%0], [%1], 16;" :: "r"(dst), "l"(src));
}
#define CP_COMMIT() asm volatile("cp.async.commit_group;" ::: "memory")
#define CP_WAIT(n)  asm volatile("cp.async.wait_group %0;" :: "n"(n) : "memory")

__device__ __forceinline__ void ldsm4(uint32_t* r, uint32_t addr) {
    asm volatile("ldmatrix.sync.aligned.m8n8.x4.shared.b16 {%0,%1,%2,%3}, [%4];"
                 : "=r"(r[0]), "=r"(r[1]), "=r"(r[2]), "=r"(r[3]) : "r"(addr));
}
__device__ __forceinline__ void mma_f16(float* c, const uint32_t* a, uint32_t b0, uint32_t b1) {
    asm volatile(
        "mma.sync.aligned.m16n8k16.row.col.f32.f16.f16.f32 "
        "{%0,%1,%2,%3}, {%4,%5,%6,%7}, {%8,%9}, {%0,%1,%2,%3};"
        : "+f"(c[0]), "+f"(c[1]), "+f"(c[2]), "+f"(c[3])
        : "r"(a[0]), "r"(a[1]), "r"(a[2]), "r"(a[3]), "r"(b0), "r"(b1));
}
// vectorized global float4 add-reduction
__device__ __forceinline__ void red4(float* dst, float x, float y, float z, float w) {
    asm volatile("red.global.add.v4.f32 [%0], {%1, %2, %3, %4};"
                 :: "l"(dst), "f"(x), "f"(y), "f"(z), "f"(w) : "memory");
}

// ---------------- zero acc + denominators ----------------
__global__ void k_zero() {
    size_t i = (size_t)blockIdx.x * blockDim.x + threadIdx.x;
    if (i < (size_t)NN * DD) g_acc[i] = 0.0f;
    if (i < 6 * NN) g_den[i] = 0.0f;
}

// ---------------- tri_rel direct (r_index[0] == arange) + exp(att logits) ----------------
__global__ void k_tri_direct(const int* __restrict__ r1, const float* __restrict__ rval,
                             const float* __restrict__ rel_emb,
                             const float* __restrict__ attn_e, const float* __restrict__ attn_r) {
    int warp = (int)(((size_t)blockIdx.x * blockDim.x + threadIdx.x) >> 5);
    int lane = threadIdx.x & 31;
    if (warp >= TT) return;
    int rel = r1[warp];
    float v = rval[warp];
    float4 a = ((const float4*)(rel_emb + (size_t)rel * DD))[lane];
    a.x *= v; a.y *= v; a.z *= v; a.w *= v;
    float ss = a.x * a.x + a.y * a.y + a.z * a.z + a.w * a.w;
    ss = warp_sum_f(ss);
    float inv = 1.0f / fmaxf(sqrtf(ss), 1e-12f);
    a.x *= inv; a.y *= inv; a.z *= inv; a.w *= inv;
    ((float4*)(g_tri + (size_t)warp * DD))[lane] = a;

    float4 k0 = ((const float4*)attn_e)[lane];
    float4 k1 = ((const float4*)(attn_e + DD))[lane];
    float4 k2 = ((const float4*)attn_r)[lane];
    float4 k3 = ((const float4*)(attn_r + DD))[lane];
    float d0 = a.x * k0.x + a.y * k0.y + a.z * k0.z + a.w * k0.w;
    float d1 = a.x * k1.x + a.y * k1.y + a.z * k1.z + a.w * k1.w;
    float d2 = a.x * k2.x + a.y * k2.y + a.z * k2.z + a.w * k2.w;
    float d3 = a.x * k3.x + a.y * k3.y + a.z * k3.z + a.w * k3.w;
    d0 = warp_sum_f(d0);
    d1 = warp_sum_f(d1);
    d2 = warp_sum_f(d2);
    d3 = warp_sum_f(d3);
    if (lane == 0) {
        g_att[0 * TT + warp] = expf(d0);
        g_att[1 * TT + warp] = expf(d1);
        g_att[2 * TT + warp] = expf(d2);
        g_att[3 * TT + warp] = expf(d3);
    }
}

// ---------------- all 6 denominators upfront (counts + 4 softmax z) ----------------
__global__ void k_denoms(const int* __restrict__ ent_rows, const int* __restrict__ rel_rows,
                         const int* __restrict__ adj_rows) {
    int e = blockIdx.x * blockDim.x + threadIdx.x;
    if (e >= TT) return;
    atomicAdd(&g_den[ent_rows[e]], 1.0f);
    atomicAdd(&g_den[NN + rel_rows[e]], 1.0f);
    int r = adj_rows[e];
#pragma unroll
    for (int l = 0; l < 4; l++)
        atomicAdd(&g_den[(2 + l) * NN + r], g_att[l * TT + e]);
}

// ---------------- sparse_mean scatter (vector red) ----------------
__global__ void k_scatter_mean(const int* __restrict__ adj, const float* __restrict__ emb) {
    int warp = (int)(((size_t)blockIdx.x * blockDim.x + threadIdx.x) >> 5);
    int lane = threadIdx.x & 31;
    if (warp >= TT) return;
    int row = adj[warp];
    int col = adj[TT + warp];
    float4 a = ((const float4*)(emb + (size_t)col * DD))[lane];
    red4(g_acc + (size_t)row * DD + lane * 4, a.x, a.y, a.z, a.w);
}

// finalize mean; zeroes g_acc; writes g_out fp32 + g_Bh fp16
__global__ void k_finalize_mean(int colofs, int cntsel) {
    size_t idx = (size_t)blockIdx.x * blockDim.x + threadIdx.x;
    if (idx >= (size_t)NN * DD) return;
    int n = (int)(idx / DD);
    int d = (int)(idx % DD);
    float c = fmaxf(g_den[cntsel * NN + n], 1.0f);
    float f = tanhf(g_acc[idx] / c);
    g_acc[idx] = 0.0f;
    g_feats[idx] = f;
    size_t o = (size_t)n * OD + colofs + d;
    g_out[o] = f;
    g_Bh[o] = __float2half_rn(f);
}

// ---------------- GAT reflected-neighbor weighted scatter (vector red) ----------------
__global__ void k_reflect(const int* __restrict__ adj, int lidx) {
    int warp = (int)(((size_t)blockIdx.x * blockDim.x + threadIdx.x) >> 5);
    int lane = threadIdx.x & 31;
    if (warp >= TT) return;
    int row = adj[warp];
    int col = adj[TT + warp];
    float w = g_att[lidx * TT + warp] / g_den[(2 + lidx) * NN + row];
    float4 t = ((const float4*)(g_tri + (size_t)warp * DD))[lane];
    float4 nb = ((const float4*)(g_feats + (size_t)col * DD))[lane];
    float s = nb.x * t.x + nb.y * t.y + nb.z * t.z + nb.w * t.w;
    s = warp_sum_f(s);
    float c2 = 2.0f * s;
    red4(g_acc + (size_t)row * DD + lane * 4,
         w * (nb.x - c2 * t.x), w * (nb.y - c2 * t.y),
         w * (nb.z - c2 * t.z), w * (nb.w - c2 * t.w));
}

// finalize tanh; zeroes g_acc; writes g_out fp32 + g_Bh fp16
__global__ void k_finalize_tanh(int colofs) {
    size_t idx = (size_t)blockIdx.x * blockDim.x + threadIdx.x;
    if (idx >= (size_t)NN * DD) return;
    int n = (int)(idx / DD);
    int d = (int)(idx % DD);
    float f = tanhf(g_acc[idx]);
    g_acc[idx] = 0.0f;
    g_feats[idx] = f;
    size_t o = (size_t)n * OD + colofs + d;
    g_out[o] = f;
    g_Bh[o] = __float2half_rn(f);
}

// ---------------- row squared norms + zero pad rows of Bh ----------------
__global__ void k_embsq() {
    int row = (int)(((size_t)blockIdx.x * blockDim.x + threadIdx.x) >> 5);
    int lane = threadIdx.x & 31;
    if (row >= NJ) return;
    if (row < NN) {
        const float4* p = (const float4*)(g_out + (size_t)row * OD);
        float ss = 0.0f;
#pragma unroll
        for (int j = lane; j < OD / 4; j += 32) {
            float4 a = p[j];
            ss += a.x * a.x + a.y * a.y + a.z * a.z + a.w * a.w;
        }
        ss = warp_sum_f(ss);
        if (lane == 0) g_embsq[row] = ss;
    } else {
        size_t o = (size_t)row * OD;
        for (int j = lane * 4; j < OD; j += 128) {
#pragma unroll
            for (int q = 0; q < 4; q++) g_Bh[o + j + q] = __float2half_rn(0.0f);
        }
    }
}

// ---------------- gather A (fp16) + pos + asq ----------------
__global__ void k_pairprep(const int* __restrict__ pairs) {
    int i = blockIdx.x;
    int li = pairs[2 * i];
    int ri = pairs[2 * i + 1];
    const float* L = g_out + (size_t)li * OD;
    const float* R = g_out + (size_t)ri * OD;
    float part = 0.0f;
    for (int c = threadIdx.x; c < OD; c += 256) {
        float a = L[c];
        float b = R[c];
        g_Ah[(size_t)i * OD + c] = __float2half_rn(a);
        g_Ah[(size_t)(i + BB) * OD + c] = __float2half_rn(b);
        float d = a - b;
        part += d * d;
    }
    __shared__ float sh[8];
    int lane = threadIdx.x & 31, wid = threadIdx.x >> 5;
    part = warp_sum_f(part);
    if (lane == 0) sh[wid] = part;
    __syncthreads();
    if (threadIdx.x == 0) {
        float s = 0.0f;
        for (int w = 0; w < 8; w++) s += sh[w];
        g_pos[i] = s;
        g_asq[i] = g_embsq[li];
        g_asq[i + BB] = g_embsq[ri];
    }
}

// ---------------- mma.sync fp16 GEMM: g_dot = A @ B^T (3-stage cp.async) ----------------
// Stage = Ah(16KB) + Bh(16KB) = 32KB; 3 stages = 96KB; 2 CTAs/SM.
__global__ __launch_bounds__(256, 2) void k_gemm_tc() {
    extern __shared__ char smraw[];
    uint32_t sm0 = smem_u32(smraw);
    uint32_t smbase = (sm0 + 1023u) & ~1023u;

    const int tid = threadIdx.x;
    const int warp = tid >> 5;
    const int lane = tid & 31;
    const int bi = blockIdx.x;   // M tile (0..31)
    const int bj = blockIdx.y;   // N tile (0..234)

    const uint4* srcs[2];
    srcs[0] = (const uint4*)g_Ah + (size_t)(bi * 128) * 96;
    srcs[1] = (const uint4*)g_Bh + (size_t)(bj * 128) * 96;

    const int frow = tid >> 3;
    const int fc = tid & 7;
#define FILL_STAGE(kc, stage)                                                    \
    do {                                                                         \
        uint32_t st_ = smbase + (uint32_t)(stage) * 32768u;                      \
        _Pragma("unroll")                                                        \
        for (int m_ = 0; m_ < 2; m_++) {                                         \
            const uint4* src_ = srcs[m_];                                        \
            uint32_t tb_ = st_ + m_ * 16384u;                                    \
            _Pragma("unroll")                                                    \
            for (int i_ = 0; i_ < 4; i_++) {                                     \
                int row_ = frow + i_ * 32;                                       \
                cp16(tb_ + swz128((uint32_t)(row_ * 128 + fc * 16)),             \
                     src_ + (size_t)row_ * 96 + (kc) * 8 + fc);                  \
            }                                                                    \
        }                                                                        \
        CP_COMMIT();                                                             \
    } while (0)

    const int wm = warp >> 2;
    const int wn = warp & 3;
    uint32_t mrow[4], brow[2];
#pragma unroll
    for (int mi = 0; mi < 4; mi++)
        mrow[mi] = (uint32_t)((wm * 64 + mi * 16 + (lane & 15)) * 128);
#pragma unroll
    for (int g = 0; g < 2; g++)
        brow[g] = (uint32_t)((wn * 32 + g * 16 + (lane & 7) + ((lane >> 3) & 1) * 8) * 128);
    const uint32_t csel = (uint32_t)(((lane >> 4) & 1) * 16);

    float acc[4][4][4];
#pragma unroll
    for (int mi = 0; mi < 4; mi++)
#pragma unroll
        for (int nj = 0; nj < 4; nj++)
#pragma unroll
            for (int q = 0; q < 4; q++) acc[mi][nj][q] = 0.0f;

    FILL_STAGE(0, 0);
    FILL_STAGE(1, 1);

    for (int k = 0; k < KCH; k++) {
        if (k + 1 < KCH) CP_WAIT(1);
        else CP_WAIT(0);
        __syncthreads();
        if (k + 2 < KCH) FILL_STAGE(k + 2, (k + 2) % 3);

        int s = k % 3;
        uint32_t Ahb = smbase + (uint32_t)s * 32768u;
        uint32_t Bhb = Ahb + 16384u;
#pragma unroll
        for (int ks = 0; ks < 4; ks++) {
            uint32_t col = (uint32_t)(ks * 32) + csel;
            uint32_t ah[4][4], bh[2][4];
#pragma unroll
            for (int mi = 0; mi < 4; mi++) ldsm4(ah[mi], Ahb + swz128(mrow[mi] + col));
#pragma unroll
            for (int g = 0; g < 2; g++) ldsm4(bh[g], Bhb + swz128(brow[g] + col));
#pragma unroll
            for (int mi = 0; mi < 4; mi++) {
#pragma unroll
                for (int nj = 0; nj < 4; nj++) {
                    int g = nj >> 1, h = nj & 1;
                    mma_f16(acc[mi][nj], ah[mi], bh[g][h], bh[g][h + 2]);
                }
            }
        }
    }

    const int mrow0 = bi * 128 + wm * 64;
    const int ncol0 = bj * 128 + wn * 32;
    const int rofs = lane >> 2;
    const int cofs = (lane & 3) * 2;
#pragma unroll
    for (int mi = 0; mi < 4; mi++) {
#pragma unroll
        for (int nj = 0; nj < 4; nj++) {
            size_t r0 = (size_t)(mrow0 + mi * 16 + rofs);
            size_t c0 = (size_t)(ncol0 + nj * 8 + cofs);
            *(float2*)(g_dot + r0 * NJ + c0) = make_float2(acc[mi][nj][0], acc[mi][nj][1]);
            *(float2*)(g_dot + (r0 + 8) * NJ + c0) = make_float2(acc[mi][nj][2], acc[mi][nj][3]);
        }
    }
#undef FILL_STAGE
}

// ---------------- fused loss pass: stats + logsumexp, row cached in SMEM ----------------
__global__ __launch_bounds__(512) void k_pass(const int* __restrict__ pairs) {
    extern __shared__ float srow[];   // NN floats
    const int i = blockIdx.x;
    const int p = i & (BB - 1);
    const int li = pairs[2 * p];
    const int ri = pairs[2 * p + 1];
    const float posg = g_pos[p] + GAMMA_C;
    const float asq = g_asq[i];
    const float* drow = g_dot + (size_t)i * NJ;

    // fp32 per-thread partials (59 elems each; |lv|<~300 -> exact enough), double at reduce
    float s = 0.0f, s2 = 0.0f, mx = -3.4e38f;
    for (int j = threadIdx.x; j < NN; j += 512) {
        float neg = asq + g_embsq[j] - 2.0f * drow[j];
        float lv = posg - neg;
        float fac = 1.0f - (float)(j == li) - (float)(j == ri);
        lv *= fac;
        srow[j] = lv;
        s += lv;
        s2 = fmaf(lv, lv, s2);
        mx = fmaxf(mx, lv);
    }
    __shared__ double sh_s[16], sh_s2[16];
    __shared__ float sh_m[16];
    __shared__ float bc_mu, bc_sc, bc_Mt;
    int lane = threadIdx.x & 31, wid = threadIdx.x >> 5;
    double ds = (double)s, ds2 = (double)s2;
#pragma unroll
    for (int o = 16; o; o >>= 1) {
        ds += __shfl_xor_sync(0xffffffffu, ds, o);
        ds2 += __shfl_xor_sync(0xffffffffu, ds2, o);
        mx = fmaxf(mx, __shfl_xor_sync(0xffffffffu, mx, o));
    }
    if (lane == 0) { sh_s[wid] = ds; sh_s2[wid] = ds2; sh_m[wid] = mx; }
    __syncthreads();
    if (threadIdx.x == 0) {
        double S = 0.0, S2 = 0.0;
        float M = -3.4e38f;
        for (int w = 0; w < 16; w++) { S += sh_s[w]; S2 += sh_s2[w]; M = fmaxf(M, sh_m[w]); }
        double mu = S / (double)NN;
        double var = S2 / (double)NN - mu * mu;
        if (var < 0.0) var = 0.0;
        float sd = (float)fmax(sqrt(var), 1e-30);
        bc_mu = (float)mu;
        bc_sc = LAMB_C / sd;
        bc_Mt = (LAMB_C / sd) * (M - (float)mu);
    }
    __syncthreads();
    const float mu = bc_mu, sc = bc_sc, Mt = bc_Mt;

    float se = 0.0f;
    for (int j = threadIdx.x; j < NN; j += 512) {
        float t = sc * (srow[j] - mu) - Mt;
        if (t > -21.0f) se += __expf(t);
    }
    double dse = (double)se;
#pragma unroll
    for (int o = 16; o; o >>= 1) dse += __shfl_xor_sync(0xffffffffu, dse, o);
    if (lane == 0) sh_s[wid] = dse;
    __syncthreads();
    if (threadIdx.x == 0) {
        double S = 0.0;
        for (int w = 0; w < 16; w++) S += sh_s[w];
        g_lse[i] = (float)((double)Mt + TAU_C + log(S));
    }
}

// ---------------- final mean ----------------
__global__ void k_final(float* __restrict__ out, int out_size) {
    double s = 0.0;
    for (int i = threadIdx.x; i < MR; i += 256) s += (double)g_lse[i];
    __shared__ double sh[8];
    int lane = threadIdx.x & 31, wid = threadIdx.x >> 5;
#pragma unroll
    for (int o = 16; o; o >>= 1) s += __shfl_xor_sync(0xffffffffu, s, o);
    if (lane == 0) sh[wid] = s;
    __syncthreads();
    if (threadIdx.x == 0) {
        double S = 0.0;
        for (int w = 0; w < 8; w++) S += sh[w];
        float val = (float)(S / (double)BB);
        for (int k = 0; k < out_size; k++) out[k] = val;
    }
}

// ---------------- host launch ----------------
extern "C" void kernel_launch(void* const* d_in, const int* in_sizes, int n_in,
                              void* d_out, int out_size) {
    const int* pairs = (const int*)d_in[0];
    const int* ent_adj = (const int*)d_in[1];
    const int* rel_adj = (const int*)d_in[2];
    const int* adj_list = (const int*)d_in[3];
    const int* r_index = (const int*)d_in[4];
    const float* r_val = (const float*)d_in[5];
    const float* ent_emb = (const float*)d_in[7];
    const float* rel_emb = (const float*)d_in[8];
    const float* attn_e = (const float*)d_in[9];
    const float* attn_r = (const float*)d_in[10];
    float* out = (float*)d_out;

    const int NT = 256;
    const int gb_acc = (int)(((size_t)NN * DD + NT - 1) / NT);
    const int gb_ew = (int)(((size_t)TT * 32 + NT - 1) / NT);
    const int gb_et = (TT + NT - 1) / NT;
    const int gb_nw = (int)(((size_t)NJ * 32 + NT - 1) / NT);

    k_tri_direct<<<gb_ew, NT>>>(r_index + TT, r_val, rel_emb, attn_e, attn_r);
    k_zero<<<gb_acc, NT>>>();
    k_denoms<<<gb_et, NT>>>(ent_adj, rel_adj, adj_list);

    // ---- GAT over ent_feature ----
    k_scatter_mean<<<gb_ew, NT>>>(ent_adj, ent_emb);
    k_finalize_mean<<<gb_acc, NT>>>(0, 0);
    for (int l = 0; l < 2; l++) {
        k_reflect<<<gb_ew, NT>>>(adj_list, l);
        k_finalize_tanh<<<gb_acc, NT>>>((l + 1) * DD);
    }

    // ---- GAT over rel_feature ----
    k_scatter_mean<<<gb_ew, NT>>>(rel_adj, rel_emb);
    k_finalize_mean<<<gb_acc, NT>>>(3 * DD, 1);
    for (int l = 0; l < 2; l++) {
        k_reflect<<<gb_ew, NT>>>(adj_list, 2 + l);
        k_finalize_tanh<<<gb_acc, NT>>>((4 + l) * DD);
    }

    // ---- align loss ----
    k_embsq<<<gb_nw, NT>>>();
    k_pairprep<<<BB, NT>>>(pairs);

    const int gemm_smem = 3 * 32768 + 1024;
    cudaFuncSetAttribute(k_gemm_tc, cudaFuncAttributeMaxDynamicSharedMemorySize, gemm_smem);
    dim3 gg(MR / 128, NJ / 128);
    k_gemm_tc<<<gg, 256, gemm_smem>>>();

    const int pass_smem = NN * (int)sizeof(float);
    cudaFuncSetAttribute(k_pass, cudaFuncAttributeMaxDynamicSharedMemorySize, pass_smem);
    k_pass<<<MR, 512, pass_smem>>>(pairs);
    k_final<<<1, 256>>>(out, out_size);
}

// round 12
// speedup vs baseline: 1.8358x; 1.0583x over previous
#include <cuda_runtime.h>
#include <cuda_fp16.h>
#include <math.h>
#include <stdint.h>

// Problem constants
#define NN 30000       // node_size
#define RR 1000        // rel_size
#define TT 200000      // triple_size
#define DD 128         // DIM
#define BB 2048        // BATCH
#define OD 768         // output feature dim (6 * 128)
#define NJ 30080       // padded column count for dot matrix (235*128)
#define MR 4096        // stacked query rows (l 0..2047, r 2048..4095)
#define GAMMA_C 3.0f
#define LAMB_C 30.0f
#define TAU_C 10.0f
#define KCH 12         // 768 / 64 K-chunks in GEMM

// ---------------- scratch (device globals; no allocation allowed) ----------------
__device__ float g_att[4 * TT];              // exp(logit) per edge: [e0, e1, r0, r1]
__device__ float g_acc[(size_t)NN * DD];
__device__ float g_den[6 * NN];              // [cnt_ent, cnt_rel, z0, z1, z2, z3]
__device__ float g_feats[(size_t)NN * DD];
__device__ float g_out[(size_t)NN * OD];
__device__ float g_embsq[NN];
__device__ float g_asq[MR];
__device__ float g_pos[BB];
__device__ float g_dot[(size_t)MR * NJ];
__device__ float g_lse[MR];
// fp16 operands (single rounding)
__device__ __align__(16) __half g_Ah[(size_t)MR * OD];
__device__ __align__(16) __half g_Bh[(size_t)NJ * OD];

// ---------------- helpers ----------------
__device__ __forceinline__ float warp_sum_f(float v) {
#pragma unroll
    for (int o = 16; o; o >>= 1) v += __shfl_xor_sync(0xffffffffu, v, o);
    return v;
}
__device__ __forceinline__ uint32_t smem_u32(const void* p) {
    uint32_t a;
    asm("{ .reg .u64 t; cvta.to.shared.u64 t, %1; cvt.u32.u64 %0, t; }" : "=r"(a) : "l"(p));
    return a;
}
__device__ __forceinline__ uint32_t swz128(uint32_t b) { return b ^ ((b >> 3) & 0x70); }

__device__ __forceinline__ void cp16(uint32_t dst, const void* src) {
    asm volatile("cp.async.cg.shared.global [%0], [%1], 16;" :: "r"(dst), "l"(src));
}
#define CP_COMMIT() asm volatile("cp.async.commit_group;" ::: "memory")
#define CP_WAIT(n)  asm volatile("cp.async.wait_group %0;" :: "n"(n) : "memory")

__device__ __forceinline__ void ldsm4(uint32_t* r, uint32_t addr) {
    asm volatile("ldmatrix.sync.aligned.m8n8.x4.shared.b16 {%0,%1,%2,%3}, [%4];"
                 : "=r"(r[0]), "=r"(r[1]), "=r"(r[2]), "=r"(r[3]) : "r"(addr));
}
__device__ __forceinline__ void mma_f16(float* c, const uint32_t* a, uint32_t b0, uint32_t b1) {
    asm volatile(
        "mma.sync.aligned.m16n8k16.row.col.f32.f16.f16.f32 "
        "{%0,%1,%2,%3}, {%4,%5,%6,%7}, {%8,%9}, {%0,%1,%2,%3};"
        : "+f"(c[0]), "+f"(c[1]), "+f"(c[2]), "+f"(c[3])
        : "r"(a[0]), "r"(a[1]), "r"(a[2]), "r"(a[3]), "r"(b0), "r"(b1));
}
// vectorized global float4 add-reduction
__device__ __forceinline__ void red4(float* dst, float x, float y, float z, float w) {
    asm volatile("red.global.add.v4.f32 [%0], {%1, %2, %3, %4};"
                 :: "l"(dst), "f"(x), "f"(y), "f"(z), "f"(w) : "memory");
}
// recompute normalized tri_rel row fragment for edge (warp-collective)
__device__ __forceinline__ float4 tri_row(const float* __restrict__ rel_emb,
                                          int rel, float v, int lane) {
    float4 a = ((const float4*)(rel_emb + (size_t)rel * DD))[lane];
    a.x *= v; a.y *= v; a.z *= v; a.w *= v;
    float ss = a.x * a.x + a.y * a.y + a.z * a.z + a.w * a.w;
    ss = warp_sum_f(ss);
    float inv = 1.0f / fmaxf(sqrtf(ss), 1e-12f);
    a.x *= inv; a.y *= inv; a.z *= inv; a.w *= inv;
    return a;
}

// ---------------- zero acc + denominators ----------------
__global__ void k_zero() {
    size_t i = (size_t)blockIdx.x * blockDim.x + threadIdx.x;
    if (i < (size_t)NN * DD) g_acc[i] = 0.0f;
    if (i < 6 * NN) g_den[i] = 0.0f;
}

// ---------------- att exps + fused denominators (counts + 4 softmax z) ----------------
__global__ void k_att(const int* __restrict__ r1, const float* __restrict__ rval,
                      const float* __restrict__ rel_emb,
                      const float* __restrict__ attn_e, const float* __restrict__ attn_r,
                      const int* __restrict__ ent_rows, const int* __restrict__ rel_rows,
                      const int* __restrict__ adj_rows) {
    int warp = (int)(((size_t)blockIdx.x * blockDim.x + threadIdx.x) >> 5);
    int lane = threadIdx.x & 31;
    if (warp >= TT) return;
    float4 a = tri_row(rel_emb, r1[warp], rval[warp], lane);

    float4 k0 = ((const float4*)attn_e)[lane];
    float4 k1 = ((const float4*)(attn_e + DD))[lane];
    float4 k2 = ((const float4*)attn_r)[lane];
    float4 k3 = ((const float4*)(attn_r + DD))[lane];
    float d0 = a.x * k0.x + a.y * k0.y + a.z * k0.z + a.w * k0.w;
    float d1 = a.x * k1.x + a.y * k1.y + a.z * k1.z + a.w * k1.w;
    float d2 = a.x * k2.x + a.y * k2.y + a.z * k2.z + a.w * k2.w;
    float d3 = a.x * k3.x + a.y * k3.y + a.z * k3.z + a.w * k3.w;
    d0 = warp_sum_f(d0);
    d1 = warp_sum_f(d1);
    d2 = warp_sum_f(d2);
    d3 = warp_sum_f(d3);
    if (lane == 0) {
        float e0 = expf(d0), e1 = expf(d1), e2 = expf(d2), e3 = expf(d3);
        g_att[0 * TT + warp] = e0;
        g_att[1 * TT + warp] = e1;
        g_att[2 * TT + warp] = e2;
        g_att[3 * TT + warp] = e3;
        atomicAdd(&g_den[ent_rows[warp]], 1.0f);
        atomicAdd(&g_den[NN + rel_rows[warp]], 1.0f);
        int r = adj_rows[warp];
        atomicAdd(&g_den[2 * NN + r], e0);
        atomicAdd(&g_den[3 * NN + r], e1);
        atomicAdd(&g_den[4 * NN + r], e2);
        atomicAdd(&g_den[5 * NN + r], e3);
    }
}

// ---------------- sparse_mean scatter (vector red) ----------------
__global__ void k_scatter_mean(const int* __restrict__ adj, const float* __restrict__ emb) {
    int warp = (int)(((size_t)blockIdx.x * blockDim.x + threadIdx.x) >> 5);
    int lane = threadIdx.x & 31;
    if (warp >= TT) return;
    int row = adj[warp];
    int col = adj[TT + warp];
    float4 a = ((const float4*)(emb + (size_t)col * DD))[lane];
    red4(g_acc + (size_t)row * DD + lane * 4, a.x, a.y, a.z, a.w);
}

// finalize mean; zeroes g_acc; writes g_out fp32 + g_Bh fp16
__global__ void k_finalize_mean(int colofs, int cntsel) {
    size_t idx = (size_t)blockIdx.x * blockDim.x + threadIdx.x;
    if (idx >= (size_t)NN * DD) return;
    int n = (int)(idx / DD);
    int d = (int)(idx % DD);
    float c = fmaxf(g_den[cntsel * NN + n], 1.0f);
    float f = tanhf(g_acc[idx] / c);
    g_acc[idx] = 0.0f;
    g_feats[idx] = f;
    size_t o = (size_t)n * OD + colofs + d;
    g_out[o] = f;
    g_Bh[o] = __float2half_rn(f);
}

// ---------------- GAT reflected-neighbor weighted scatter (tri recomputed) ----------------
__global__ void k_reflect(const int* __restrict__ adj, int lidx,
                          const int* __restrict__ r1, const float* __restrict__ rval,
                          const float* __restrict__ rel_emb) {
    int warp = (int)(((size_t)blockIdx.x * blockDim.x + threadIdx.x) >> 5);
    int lane = threadIdx.x & 31;
    if (warp >= TT) return;
    int row = adj[warp];
    int col = adj[TT + warp];
    float w = g_att[lidx * TT + warp] / g_den[(2 + lidx) * NN + row];
    float4 t = tri_row(rel_emb, r1[warp], rval[warp], lane);
    float4 nb = ((const float4*)(g_feats + (size_t)col * DD))[lane];
    float s = nb.x * t.x + nb.y * t.y + nb.z * t.z + nb.w * t.w;
    s = warp_sum_f(s);
    float c2 = 2.0f * s;
    red4(g_acc + (size_t)row * DD + lane * 4,
         w * (nb.x - c2 * t.x), w * (nb.y - c2 * t.y),
         w * (nb.z - c2 * t.z), w * (nb.w - c2 * t.w));
}

// finalize tanh; zeroes g_acc; writes g_out fp32 + g_Bh fp16
__global__ void k_finalize_tanh(int colofs) {
    size_t idx = (size_t)blockIdx.x * blockDim.x + threadIdx.x;
    if (idx >= (size_t)NN * DD) return;
    int n = (int)(idx / DD);
    int d = (int)(idx % DD);
    float f = tanhf(g_acc[idx]);
    g_acc[idx] = 0.0f;
    g_feats[idx] = f;
    size_t o = (size_t)n * OD + colofs + d;
    g_out[o] = f;
    g_Bh[o] = __float2half_rn(f);
}

// ---------------- row squared norms + zero pad rows of Bh ----------------
__global__ void k_embsq() {
    int row = (int)(((size_t)blockIdx.x * blockDim.x + threadIdx.x) >> 5);
    int lane = threadIdx.x & 31;
    if (row >= NJ) return;
    if (row < NN) {
        const float4* p = (const float4*)(g_out + (size_t)row * OD);
        float ss = 0.0f;
#pragma unroll
        for (int j = lane; j < OD / 4; j += 32) {
            float4 a = p[j];
            ss += a.x * a.x + a.y * a.y + a.z * a.z + a.w * a.w;
        }
        ss = warp_sum_f(ss);
        if (lane == 0) g_embsq[row] = ss;
    } else {
        size_t o = (size_t)row * OD;
        for (int j = lane * 4; j < OD; j += 128) {
#pragma unroll
            for (int q = 0; q < 4; q++) g_Bh[o + j + q] = __float2half_rn(0.0f);
        }
    }
}

// ---------------- gather A (fp16) + pos + asq ----------------
__global__ void k_pairprep(const int* __restrict__ pairs) {
    int i = blockIdx.x;
    int li = pairs[2 * i];
    int ri = pairs[2 * i + 1];
    const float* L = g_out + (size_t)li * OD;
    const float* R = g_out + (size_t)ri * OD;
    float part = 0.0f;
    for (int c = threadIdx.x; c < OD; c += 256) {
        float a = L[c];
        float b = R[c];
        g_Ah[(size_t)i * OD + c] = __float2half_rn(a);
        g_Ah[(size_t)(i + BB) * OD + c] = __float2half_rn(b);
        float d = a - b;
        part += d * d;
    }
    __shared__ float sh[8];
    int lane = threadIdx.x & 31, wid = threadIdx.x >> 5;
    part = warp_sum_f(part);
    if (lane == 0) sh[wid] = part;
    __syncthreads();
    if (threadIdx.x == 0) {
        float s = 0.0f;
        for (int w = 0; w < 8; w++) s += sh[w];
        g_pos[i] = s;
        g_asq[i] = g_embsq[li];
        g_asq[i + BB] = g_embsq[ri];
    }
}

// ---------------- mma.sync fp16 GEMM: g_dot = A @ B^T (3-stage cp.async) ----------------
__global__ __launch_bounds__(256, 2) void k_gemm_tc() {
    extern __shared__ char smraw[];
    uint32_t sm0 = smem_u32(smraw);
    uint32_t smbase = (sm0 + 1023u) & ~1023u;

    const int tid = threadIdx.x;
    const int warp = tid >> 5;
    const int lane = tid & 31;
    const int bi = blockIdx.x;   // M tile (0..31)
    const int bj = blockIdx.y;   // N tile (0..234)

    const uint4* srcs[2];
    srcs[0] = (const uint4*)g_Ah + (size_t)(bi * 128) * 96;
    srcs[1] = (const uint4*)g_Bh + (size_t)(bj * 128) * 96;

    const int frow = tid >> 3;
    const int fc = tid & 7;
#define FILL_STAGE(kc, stage)                                                    \
    do {                                                                         \
        uint32_t st_ = smbase + (uint32_t)(stage) * 32768u;                      \
        _Pragma("unroll")                                                        \
        for (int m_ = 0; m_ < 2; m_++) {                                         \
            const uint4* src_ = srcs[m_];                                        \
            uint32_t tb_ = st_ + m_ * 16384u;                                    \
            _Pragma("unroll")                                                    \
            for (int i_ = 0; i_ < 4; i_++) {                                     \
                int row_ = frow + i_ * 32;                                       \
                cp16(tb_ + swz128((uint32_t)(row_ * 128 + fc * 16)),             \
                     src_ + (size_t)row_ * 96 + (kc) * 8 + fc);                  \
            }                                                                    \
        }                                                                        \
        CP_COMMIT();                                                             \
    } while (0)

    const int wm = warp >> 2;
    const int wn = warp & 3;
    uint32_t mrow[4], brow[2];
#pragma unroll
    for (int mi = 0; mi < 4; mi++)
        mrow[mi] = (uint32_t)((wm * 64 + mi * 16 + (lane & 15)) * 128);
#pragma unroll
    for (int g = 0; g < 2; g++)
        brow[g] = (uint32_t)((wn * 32 + g * 16 + (lane & 7) + ((lane >> 3) & 1) * 8) * 128);
    const uint32_t csel = (uint32_t)(((lane >> 4) & 1) * 16);

    float acc[4][4][4];
#pragma unroll
    for (int mi = 0; mi < 4; mi++)
#pragma unroll
        for (int nj = 0; nj < 4; nj++)
#pragma unroll
            for (int q = 0; q < 4; q++) acc[mi][nj][q] = 0.0f;

    FILL_STAGE(0, 0);
    FILL_STAGE(1, 1);

    for (int k = 0; k < KCH; k++) {
        if (k + 1 < KCH) CP_WAIT(1);
        else CP_WAIT(0);
        __syncthreads();
        if (k + 2 < KCH) FILL_STAGE(k + 2, (k + 2) % 3);

        int s = k % 3;
        uint32_t Ahb = smbase + (uint32_t)s * 32768u;
        uint32_t Bhb = Ahb + 16384u;
#pragma unroll
        for (int ks = 0; ks < 4; ks++) {
            uint32_t col = (uint32_t)(ks * 32) + csel;
            uint32_t ah[4][4], bh[2][4];
#pragma unroll
            for (int mi = 0; mi < 4; mi++) ldsm4(ah[mi], Ahb + swz128(mrow[mi] + col));
#pragma unroll
            for (int g = 0; g < 2; g++) ldsm4(bh[g], Bhb + swz128(brow[g] + col));
#pragma unroll
            for (int mi = 0; mi < 4; mi++) {
#pragma unroll
                for (int nj = 0; nj < 4; nj++) {
                    int g = nj >> 1, h = nj & 1;
                    mma_f16(acc[mi][nj], ah[mi], bh[g][h], bh[g][h + 2]);
                }
            }
        }
    }

    const int mrow0 = bi * 128 + wm * 64;
    const int ncol0 = bj * 128 + wn * 32;
    const int rofs = lane >> 2;
    const int cofs = (lane & 3) * 2;
#pragma unroll
    for (int mi = 0; mi < 4; mi++) {
#pragma unroll
        for (int nj = 0; nj < 4; nj++) {
            size_t r0 = (size_t)(mrow0 + mi * 16 + rofs);
            size_t c0 = (size_t)(ncol0 + nj * 8 + cofs);
            *(float2*)(g_dot + r0 * NJ + c0) = make_float2(acc[mi][nj][0], acc[mi][nj][1]);
            *(float2*)(g_dot + (r0 + 8) * NJ + c0) = make_float2(acc[mi][nj][2], acc[mi][nj][3]);
        }
    }
#undef FILL_STAGE
}

// ---------------- fused loss pass: stats + logsumexp, row cached in SMEM ----------------
__global__ __launch_bounds__(1024) void k_pass(const int* __restrict__ pairs) {
    extern __shared__ float srow[];   // NN floats
    const int i = blockIdx.x;
    const int p = i & (BB - 1);
    const int li = pairs[2 * p];
    const int ri = pairs[2 * p + 1];
    const float posg = g_pos[p] + GAMMA_C;
    const float asq = g_asq[i];
    const float* drow = g_dot + (size_t)i * NJ;

    float s = 0.0f, s2 = 0.0f, mx = -3.4e38f;
    for (int j = threadIdx.x; j < NN; j += 1024) {
        float neg = asq + g_embsq[j] - 2.0f * drow[j];
        float lv = posg - neg;
        float fac = 1.0f - (float)(j == li) - (float)(j == ri);
        lv *= fac;
        srow[j] = lv;
        s += lv;
        s2 = fmaf(lv, lv, s2);
        mx = fmaxf(mx, lv);
    }
    __shared__ double sh_s[32], sh_s2[32];
    __shared__ float sh_m[32];
    __shared__ float bc_mu, bc_sc, bc_Mt;
    int lane = threadIdx.x & 31, wid = threadIdx.x >> 5;
    double ds = (double)s, ds2 = (double)s2;
#pragma unroll
    for (int o = 16; o; o >>= 1) {
        ds += __shfl_xor_sync(0xffffffffu, ds, o);
        ds2 += __shfl_xor_sync(0xffffffffu, ds2, o);
        mx = fmaxf(mx, __shfl_xor_sync(0xffffffffu, mx, o));
    }
    if (lane == 0) { sh_s[wid] = ds; sh_s2[wid] = ds2; sh_m[wid] = mx; }
    __syncthreads();
    if (threadIdx.x == 0) {
        double S = 0.0, S2 = 0.0;
        float M = -3.4e38f;
        for (int w = 0; w < 32; w++) { S += sh_s[w]; S2 += sh_s2[w]; M = fmaxf(M, sh_m[w]); }
        double mu = S / (double)NN;
        double var = S2 / (double)NN - mu * mu;
        if (var < 0.0) var = 0.0;
        float sd = (float)fmax(sqrt(var), 1e-30);
        bc_mu = (float)mu;
        bc_sc = LAMB_C / sd;
        bc_Mt = (LAMB_C / sd) * (M - (float)mu);
    }
    __syncthreads();
    const float mu = bc_mu, sc = bc_sc, Mt = bc_Mt;

    float se = 0.0f;
    for (int j = threadIdx.x; j < NN; j += 1024) {
        float t = sc * (srow[j] - mu) - Mt;
        if (t > -21.0f) se += __expf(t);
    }
    double dse = (double)se;
#pragma unroll
    for (int o = 16; o; o >>= 1) dse += __shfl_xor_sync(0xffffffffu, dse, o);
    if (lane == 0) sh_s[wid] = dse;
    __syncthreads();
    if (threadIdx.x == 0) {
        double S = 0.0;
        for (int w = 0; w < 32; w++) S += sh_s[w];
        g_lse[i] = (float)((double)Mt + TAU_C + log(S));
    }
}

// ---------------- final mean ----------------
__global__ void k_final(float* __restrict__ out, int out_size) {
    double s = 0.0;
    for (int i = threadIdx.x; i < MR; i += 256) s += (double)g_lse[i];
    __shared__ double sh[8];
    int lane = threadIdx.x & 31, wid = threadIdx.x >> 5;
#pragma unroll
    for (int o = 16; o; o >>= 1) s += __shfl_xor_sync(0xffffffffu, s, o);
    if (lane == 0) sh[wid] = s;
    __syncthreads();
    if (threadIdx.x == 0) {
        double S = 0.0;
        for (int w = 0; w < 8; w++) S += sh[w];
        float val = (float)(S / (double)BB);
        for (int k = 0; k < out_size; k++) out[k] = val;
    }
}

// ---------------- host launch ----------------
extern "C" void kernel_launch(void* const* d_in, const int* in_sizes, int n_in,
                              void* d_out, int out_size) {
    const int* pairs = (const int*)d_in[0];
    const int* ent_adj = (const int*)d_in[1];
    const int* rel_adj = (const int*)d_in[2];
    const int* adj_list = (const int*)d_in[3];
    const int* r_index = (const int*)d_in[4];
    const float* r_val = (const float*)d_in[5];
    const float* ent_emb = (const float*)d_in[7];
    const float* rel_emb = (const float*)d_in[8];
    const float* attn_e = (const float*)d_in[9];
    const float* attn_r = (const float*)d_in[10];
    float* out = (float*)d_out;

    const int NT = 256;
    const int gb_acc = (int)(((size_t)NN * DD + NT - 1) / NT);
    const int gb_ew = (int)(((size_t)TT * 32 + NT - 1) / NT);
    const int gb_nw = (int)(((size_t)NJ * 32 + NT - 1) / NT);

    k_zero<<<gb_acc, NT>>>();
    k_att<<<gb_ew, NT>>>(r_index + TT, r_val, rel_emb, attn_e, attn_r,
                         ent_adj, rel_adj, adj_list);

    // ---- GAT over ent_feature ----
    k_scatter_mean<<<gb_ew, NT>>>(ent_adj, ent_emb);
    k_finalize_mean<<<gb_acc, NT>>>(0, 0);
    for (int l = 0; l < 2; l++) {
        k_reflect<<<gb_ew, NT>>>(adj_list, l, r_index + TT, r_val, rel_emb);
        k_finalize_tanh<<<gb_acc, NT>>>((l + 1) * DD);
    }

    // ---- GAT over rel_feature ----
    k_scatter_mean<<<gb_ew, NT>>>(rel_adj, rel_emb);
    k_finalize_mean<<<gb_acc, NT>>>(3 * DD, 1);
    for (int l = 0; l < 2; l++) {
        k_reflect<<<gb_ew, NT>>>(adj_list, 2 + l, r_index + TT, r_val, rel_emb);
        k_finalize_tanh<<<gb_acc, NT>>>((4 + l) * DD);
    }

    // ---- align loss ----
    k_embsq<<<gb_nw, NT>>>();
    k_pairprep<<<BB, NT>>>(pairs);

    const int gemm_smem = 3 * 32768 + 1024;
    cudaFuncSetAttribute(k_gemm_tc, cudaFuncAttributeMaxDynamicSharedMemorySize, gemm_smem);
    dim3 gg(MR / 128, NJ / 128);
    k_gemm_tc<<<gg, 256, gemm_smem>>>();

    const int pass_smem = NN * (int)sizeof(float);
    cudaFuncSetAttribute(k_pass, cudaFuncAttributeMaxDynamicSharedMemorySize, pass_smem);
    k_pass<<<MR, 1024, pass_smem>>>(pairs);
    k_final<<<1, 256>>>(out, out_size);
}

// round 14
// speedup vs baseline: 2.5811x; 1.4060x over previous
#include <cuda_runtime.h>
#include <cuda_fp16.h>
#include <math.h>
#include <stdint.h>

// Problem constants
#define NN 30000
#define RR 1000
#define TT 200000
#define DD 128
#define BB 2048
#define OD 768
#define NJ 30080
#define MR 4096
#define GAMMA_C 3.0f
#define LAMB_C 30.0f
#define TAU_C 10.0f
#define KCH 12

// ---------------- scratch ----------------
__device__ float g_att[4 * TT];
__device__ float g_acc[(size_t)NN * DD];    // ent chain accumulator
__device__ float g_acc2[(size_t)NN * DD];   // rel chain accumulator
__device__ float g_den[6 * NN];             // [cnt_ent, cnt_rel, z0, z1, z2, z3]
__device__ float g_feats[(size_t)NN * DD];  // ent chain feats
__device__ float g_feats2[(size_t)NN * DD]; // rel chain feats
__device__ float g_out[(size_t)NN * OD];
__device__ float g_embsq[NN];
__device__ float g_asq[MR];
__device__ float g_pos[BB];
__device__ int2  g_lr[MR];
__device__ float g_dot[(size_t)MR * NJ];
__device__ float g_lse[MR];
// per-row loss stats (accumulated by GEMM epilogue)
__device__ float g_s[MR];
__device__ float g_s2[MR];
__device__ unsigned g_mxu[MR];
__device__ float g_muv[MR], g_scv[MR], g_Mtv[MR];
// fp16 operands
__device__ __align__(16) __half g_Ah[(size_t)MR * OD];
__device__ __align__(16) __half g_Bh[(size_t)NJ * OD];

// ---------------- helpers ----------------
__device__ __forceinline__ float warp_sum_f(float v) {
#pragma unroll
    for (int o = 16; o; o >>= 1) v += __shfl_xor_sync(0xffffffffu, v, o);
    return v;
}
__device__ __forceinline__ uint32_t smem_u32(const void* p) {
    uint32_t a;
    asm("{ .reg .u64 t; cvta.to.shared.u64 t, %1; cvt.u32.u64 %0, t; }" : "=r"(a) : "l"(p));
    return a;
}
__device__ __forceinline__ uint32_t swz128(uint32_t b) { return b ^ ((b >> 3) & 0x70); }

__device__ __forceinline__ void cp16(uint32_t dst, const void* src) {
    asm volatile("cp.async.cg.shared.global [%0], [%1], 16;" :: "r"(dst), "l"(src));
}
#define CP_COMMIT() asm volatile("cp.async.commit_group;" ::: "memory")
#define CP_WAIT(n)  asm volatile("cp.async.wait_group %0;" :: "n"(n) : "memory")

__device__ __forceinline__ void ldsm4(uint32_t* r, uint32_t addr) {
    asm volatile("ldmatrix.sync.aligned.m8n8.x4.shared.b16 {%0,%1,%2,%3}, [%4];"
                 : "=r"(r[0]), "=r"(r[1]), "=r"(r[2]), "=r"(r[3]) : "r"(addr));
}
__device__ __forceinline__ void mma_f16(float* c, const uint32_t* a, uint32_t b0, uint32_t b1) {
    asm volatile(
        "mma.sync.aligned.m16n8k16.row.col.f32.f16.f16.f32 "
        "{%0,%1,%2,%3}, {%4,%5,%6,%7}, {%8,%9}, {%0,%1,%2,%3};"
        : "+f"(c[0]), "+f"(c[1]), "+f"(c[2]), "+f"(c[3])
        : "r"(a[0]), "r"(a[1]), "r"(a[2]), "r"(a[3]), "r"(b0), "r"(b1));
}
__device__ __forceinline__ void red4(float* dst, float x, float y, float z, float w) {
    asm volatile("red.global.add.v4.f32 [%0], {%1, %2, %3, %4};"
                 :: "l"(dst), "f"(x), "f"(y), "f"(z), "f"(w) : "memory");
}
// ordered-uint encoding for float atomicMax
__device__ __forceinline__ unsigned fenc(float f) {
    unsigned u = __float_as_uint(f);
    return (u & 0x80000000u) ? ~u : (u | 0x80000000u);
}
__device__ __forceinline__ float fdec(unsigned k) {
    unsigned u = (k & 0x80000000u) ? (k & 0x7FFFFFFFu) : ~k;
    return __uint_as_float(u);
}
// recompute normalized tri_rel row fragment (warp-collective)
__device__ __forceinline__ float4 tri_row(const float* __restrict__ rel_emb,
                                          int rel, float v, int lane) {
    float4 a = ((const float4*)(rel_emb + (size_t)rel * DD))[lane];
    a.x *= v; a.y *= v; a.z *= v; a.w *= v;
    float ss = a.x * a.x + a.y * a.y + a.z * a.z + a.w * a.w;
    ss = warp_sum_f(ss);
    float inv = 1.0f / fmaxf(sqrtf(ss), 1e-12f);
    a.x *= inv; a.y *= inv; a.z *= inv; a.w *= inv;
    return a;
}

// ---------------- zero scratch ----------------
__global__ void k_zero() {
    size_t i = (size_t)blockIdx.x * blockDim.x + threadIdx.x;
    if (i < (size_t)NN * DD) { g_acc[i] = 0.0f; g_acc2[i] = 0.0f; }
    if (i < 6 * NN) g_den[i] = 0.0f;
    if (i < MR) { g_s[i] = 0.0f; g_s2[i] = 0.0f; g_mxu[i] = 0u; }
}

// ---------------- att exps + fused denominators ----------------
__global__ void k_att(const int* __restrict__ r1, const float* __restrict__ rval,
                      const float* __restrict__ rel_emb,
                      const float* __restrict__ attn_e, const float* __restrict__ attn_r,
                      const int* __restrict__ ent_rows, const int* __restrict__ rel_rows,
                      const int* __restrict__ adj_rows) {
    int warp = (int)(((size_t)blockIdx.x * blockDim.x + threadIdx.x) >> 5);
    int lane = threadIdx.x & 31;
    if (warp >= TT) return;
    float4 a = tri_row(rel_emb, r1[warp], rval[warp], lane);

    float4 k0 = ((const float4*)attn_e)[lane];
    float4 k1 = ((const float4*)(attn_e + DD))[lane];
    float4 k2 = ((const float4*)attn_r)[lane];
    float4 k3 = ((const float4*)(attn_r + DD))[lane];
    float d0 = a.x * k0.x + a.y * k0.y + a.z * k0.z + a.w * k0.w;
    float d1 = a.x * k1.x + a.y * k1.y + a.z * k1.z + a.w * k1.w;
    float d2 = a.x * k2.x + a.y * k2.y + a.z * k2.z + a.w * k2.w;
    float d3 = a.x * k3.x + a.y * k3.y + a.z * k3.z + a.w * k3.w;
    d0 = warp_sum_f(d0);
    d1 = warp_sum_f(d1);
    d2 = warp_sum_f(d2);
    d3 = warp_sum_f(d3);
    if (lane == 0) {
        float e0 = expf(d0), e1 = expf(d1), e2 = expf(d2), e3 = expf(d3);
        g_att[0 * TT + warp] = e0;
        g_att[1 * TT + warp] = e1;
        g_att[2 * TT + warp] = e2;
        g_att[3 * TT + warp] = e3;
        atomicAdd(&g_den[ent_rows[warp]], 1.0f);
        atomicAdd(&g_den[NN + rel_rows[warp]], 1.0f);
        int r = adj_rows[warp];
        atomicAdd(&g_den[2 * NN + r], e0);
        atomicAdd(&g_den[3 * NN + r], e1);
        atomicAdd(&g_den[4 * NN + r], e2);
        atomicAdd(&g_den[5 * NN + r], e3);
    }
}

// ---------------- both sparse_mean scatters in one kernel ----------------
__global__ void k_scatter_mean2(const int* __restrict__ ent_adj, const float* __restrict__ ent_emb,
                                const int* __restrict__ rel_adj, const float* __restrict__ rel_emb) {
    int warp = (int)(((size_t)blockIdx.x * blockDim.x + threadIdx.x) >> 5);
    int lane = threadIdx.x & 31;
    if (warp >= TT) return;
    {
        int row = ent_adj[warp];
        int col = ent_adj[TT + warp];
        float4 a = ((const float4*)(ent_emb + (size_t)col * DD))[lane];
        red4(g_acc + (size_t)row * DD + lane * 4, a.x, a.y, a.z, a.w);
    }
    {
        int row = rel_adj[warp];
        int col = rel_adj[TT + warp];
        float4 a = ((const float4*)(rel_emb + (size_t)col * DD))[lane];
        red4(g_acc2 + (size_t)row * DD + lane * 4, a.x, a.y, a.z, a.w);
    }
}

// finalize mean for BOTH chains; zeroes accs; writes g_out + g_Bh
__global__ void k_finalize_mean2() {
    size_t idx = (size_t)blockIdx.x * blockDim.x + threadIdx.x;
    if (idx >= (size_t)NN * DD) return;
    int n = (int)(idx / DD);
    int d = (int)(idx % DD);
    float ce = fmaxf(g_den[n], 1.0f);
    float cr = fmaxf(g_den[NN + n], 1.0f);
    float fe = tanhf(g_acc[idx] / ce);
    float fr = tanhf(g_acc2[idx] / cr);
    g_acc[idx] = 0.0f;
    g_acc2[idx] = 0.0f;
    g_feats[idx] = fe;
    g_feats2[idx] = fr;
    size_t oe = (size_t)n * OD + d;
    size_t orr = (size_t)n * OD + 3 * DD + d;
    g_out[oe] = fe;  g_Bh[oe] = __float2half_rn(fe);
    g_out[orr] = fr; g_Bh[orr] = __float2half_rn(fr);
}

// ---------------- dual reflected-neighbor scatter (tri computed once) ----------------
__global__ void k_reflect2(const int* __restrict__ adj, int l,
                           const int* __restrict__ r1, const float* __restrict__ rval,
                           const float* __restrict__ rel_emb) {
    int warp = (int)(((size_t)blockIdx.x * blockDim.x + threadIdx.x) >> 5);
    int lane = threadIdx.x & 31;
    if (warp >= TT) return;
    int row = adj[warp];
    int col = adj[TT + warp];
    float we = g_att[l * TT + warp] / g_den[(2 + l) * NN + row];
    float wr = g_att[(2 + l) * TT + warp] / g_den[(4 + l) * NN + row];
    float4 t = tri_row(rel_emb, r1[warp], rval[warp], lane);
    float4 ne = ((const float4*)(g_feats + (size_t)col * DD))[lane];
    float4 nr = ((const float4*)(g_feats2 + (size_t)col * DD))[lane];
    float se = ne.x * t.x + ne.y * t.y + ne.z * t.z + ne.w * t.w;
    float sr = nr.x * t.x + nr.y * t.y + nr.z * t.z + nr.w * t.w;
#pragma unroll
    for (int o = 16; o; o >>= 1) {
        se += __shfl_xor_sync(0xffffffffu, se, o);
        sr += __shfl_xor_sync(0xffffffffu, sr, o);
    }
    float ce = 2.0f * se, cr = 2.0f * sr;
    red4(g_acc + (size_t)row * DD + lane * 4,
         we * (ne.x - ce * t.x), we * (ne.y - ce * t.y),
         we * (ne.z - ce * t.z), we * (ne.w - ce * t.w));
    red4(g_acc2 + (size_t)row * DD + lane * 4,
         wr * (nr.x - cr * t.x), wr * (nr.y - cr * t.y),
         wr * (nr.z - cr * t.z), wr * (nr.w - cr * t.w));
}

// finalize tanh for BOTH chains; zeroes accs
__global__ void k_finalize_tanh2(int l) {
    size_t idx = (size_t)blockIdx.x * blockDim.x + threadIdx.x;
    if (idx >= (size_t)NN * DD) return;
    int n = (int)(idx / DD);
    int d = (int)(idx % DD);
    float fe = tanhf(g_acc[idx]);
    float fr = tanhf(g_acc2[idx]);
    g_acc[idx] = 0.0f;
    g_acc2[idx] = 0.0f;
    g_feats[idx] = fe;
    g_feats2[idx] = fr;
    size_t oe = (size_t)n * OD + (l + 1) * DD + d;
    size_t orr = (size_t)n * OD + (4 + l) * DD + d;
    g_out[oe] = fe;  g_Bh[oe] = __float2half_rn(fe);
    g_out[orr] = fr; g_Bh[orr] = __float2half_rn(fr);
}

// ---------------- row squared norms + zero pad rows of Bh ----------------
__global__ void k_embsq() {
    int row = (int)(((size_t)blockIdx.x * blockDim.x + threadIdx.x) >> 5);
    int lane = threadIdx.x & 31;
    if (row >= NJ) return;
    if (row < NN) {
        const float4* p = (const float4*)(g_out + (size_t)row * OD);
        float ss = 0.0f;
#pragma unroll
        for (int j = lane; j < OD / 4; j += 32) {
            float4 a = p[j];
            ss += a.x * a.x + a.y * a.y + a.z * a.z + a.w * a.w;
        }
        ss = warp_sum_f(ss);
        if (lane == 0) g_embsq[row] = ss;
    } else {
        size_t o = (size_t)row * OD;
        for (int j = lane * 4; j < OD; j += 128) {
#pragma unroll
            for (int q = 0; q < 4; q++) g_Bh[o + j + q] = __float2half_rn(0.0f);
        }
    }
}

// ---------------- gather A (fp16) + pos + asq + lr ----------------
__global__ void k_pairprep(const int* __restrict__ pairs) {
    int i = blockIdx.x;
    int li = pairs[2 * i];
    int ri = pairs[2 * i + 1];
    const float* L = g_out + (size_t)li * OD;
    const float* R = g_out + (size_t)ri * OD;
    float part = 0.0f;
    for (int c = threadIdx.x; c < OD; c += 256) {
        float a = L[c];
        float b = R[c];
        g_Ah[(size_t)i * OD + c] = __float2half_rn(a);
        g_Ah[(size_t)(i + BB) * OD + c] = __float2half_rn(b);
        float d = a - b;
        part += d * d;
    }
    __shared__ float sh[8];
    int lane = threadIdx.x & 31, wid = threadIdx.x >> 5;
    part = warp_sum_f(part);
    if (lane == 0) sh[wid] = part;
    __syncthreads();
    if (threadIdx.x == 0) {
        float s = 0.0f;
        for (int w = 0; w < 8; w++) s += sh[w];
        g_pos[i] = s;
        g_asq[i] = g_embsq[li];
        g_asq[i + BB] = g_embsq[ri];
        g_lr[i] = make_int2(li, ri);
        g_lr[i + BB] = make_int2(li, ri);
    }
}

// ---------------- fp16 GEMM + fused per-row loss stats in epilogue ----------------
__global__ __launch_bounds__(256, 2) void k_gemm_tc() {
    extern __shared__ char smraw[];
    uint32_t sm0 = smem_u32(smraw);
    uint32_t smbase = (sm0 + 1023u) & ~1023u;

    const int tid = threadIdx.x;
    const int warp = tid >> 5;
    const int lane = tid & 31;
    const int bi = blockIdx.x;
    const int bj = blockIdx.y;

    const uint4* srcs[2];
    srcs[0] = (const uint4*)g_Ah + (size_t)(bi * 128) * 96;
    srcs[1] = (const uint4*)g_Bh + (size_t)(bj * 128) * 96;

    const int frow = tid >> 3;
    const int fc = tid & 7;
#define FILL_STAGE(kc, stage)                                                    \
    do {                                                                         \
        uint32_t st_ = smbase + (uint32_t)(stage) * 32768u;                      \
        _Pragma("unroll")                                                        \
        for (int m_ = 0; m_ < 2; m_++) {                                         \
            const uint4* src_ = srcs[m_];                                        \
            uint32_t tb_ = st_ + m_ * 16384u;                                    \
            _Pragma("unroll")                                                    \
            for (int i_ = 0; i_ < 4; i_++) {                                     \
                int row_ = frow + i_ * 32;                                       \
                cp16(tb_ + swz128((uint32_t)(row_ * 128 + fc * 16)),             \
                     src_ + (size_t)row_ * 96 + (kc) * 8 + fc);                  \
            }                                                                    \
        }                                                                        \
        CP_COMMIT();                                                             \
    } while (0)

    const int wm = warp >> 2;
    const int wn = warp & 3;
    uint32_t mrow[4], brow[2];
#pragma unroll
    for (int mi = 0; mi < 4; mi++)
        mrow[mi] = (uint32_t)((wm * 64 + mi * 16 + (lane & 15)) * 128);
#pragma unroll
    for (int g = 0; g < 2; g++)
        brow[g] = (uint32_t)((wn * 32 + g * 16 + (lane & 7) + ((lane >> 3) & 1) * 8) * 128);
    const uint32_t csel = (uint32_t)(((lane >> 4) & 1) * 16);

    float acc[4][4][4];
#pragma unroll
    for (int mi = 0; mi < 4; mi++)
#pragma unroll
        for (int nj = 0; nj < 4; nj++)
#pragma unroll
            for (int q = 0; q < 4; q++) acc[mi][nj][q] = 0.0f;

    FILL_STAGE(0, 0);
    FILL_STAGE(1, 1);

    for (int k = 0; k < KCH; k++) {
        if (k + 1 < KCH) CP_WAIT(1);
        else CP_WAIT(0);
        __syncthreads();
        if (k + 2 < KCH) FILL_STAGE(k + 2, (k + 2) % 3);

        int s = k % 3;
        uint32_t Ahb = smbase + (uint32_t)s * 32768u;
        uint32_t Bhb = Ahb + 16384u;
#pragma unroll
        for (int ks = 0; ks < 4; ks++) {
            uint32_t col = (uint32_t)(ks * 32) + csel;
            uint32_t ah[4][4], bh[2][4];
#pragma unroll
            for (int mi = 0; mi < 4; mi++) ldsm4(ah[mi], Ahb + swz128(mrow[mi] + col));
#pragma unroll
            for (int g = 0; g < 2; g++) ldsm4(bh[g], Bhb + swz128(brow[g] + col));
#pragma unroll
            for (int mi = 0; mi < 4; mi++) {
#pragma unroll
                for (int nj = 0; nj < 4; nj++) {
                    int g = nj >> 1, h = nj & 1;
                    mma_f16(acc[mi][nj], ah[mi], bh[g][h], bh[g][h + 2]);
                }
            }
        }
    }

    // epilogue: write dot + accumulate per-row loss stats
    const int mrow0 = bi * 128 + wm * 64;
    const int ncol0 = bj * 128 + wn * 32;
    const int rofs = lane >> 2;
    const int cofs = (lane & 3) * 2;
#pragma unroll
    for (int mi = 0; mi < 4; mi++) {
        int r0 = mrow0 + mi * 16 + rofs;
        int r1 = r0 + 8;
        int2 lr0 = g_lr[r0];
        int2 lr1 = g_lr[r1];
        float pa0 = g_pos[r0 & (BB - 1)] + GAMMA_C - g_asq[r0];
        float pa1 = g_pos[r1 & (BB - 1)] + GAMMA_C - g_asq[r1];
        float s0 = 0.0f, q0 = 0.0f, m0 = -3.4e38f;
        float s1 = 0.0f, q1 = 0.0f, m1 = -3.4e38f;
#pragma unroll
        for (int nj = 0; nj < 4; nj++) {
            int cbase = ncol0 + nj * 8 + cofs;
            size_t c0 = (size_t)cbase;
            *(float2*)(g_dot + (size_t)r0 * NJ + c0) = make_float2(acc[mi][nj][0], acc[mi][nj][1]);
            *(float2*)(g_dot + (size_t)r1 * NJ + c0) = make_float2(acc[mi][nj][2], acc[mi][nj][3]);
#pragma unroll
            for (int q = 0; q < 2; q++) {
                int j = cbase + q;
                if (j < NN) {
                    float e = g_embsq[j];
                    float fac0 = 1.0f - (float)(j == lr0.x) - (float)(j == lr0.y);
                    float lv0 = (pa0 - e + 2.0f * acc[mi][nj][q]) * fac0;
                    s0 += lv0; q0 = fmaf(lv0, lv0, q0); m0 = fmaxf(m0, lv0);
                    float fac1 = 1.0f - (float)(j == lr1.x) - (float)(j == lr1.y);
                    float lv1 = (pa1 - e + 2.0f * acc[mi][nj][2 + q]) * fac1;
                    s1 += lv1; q1 = fmaf(lv1, lv1, q1); m1 = fmaxf(m1, lv1);
                }
            }
        }
        // reduce across the 4 threads sharing each row
#pragma unroll
        for (int o = 1; o <= 2; o <<= 1) {
            s0 += __shfl_xor_sync(0xffffffffu, s0, o);
            q0 += __shfl_xor_sync(0xffffffffu, q0, o);
            m0 = fmaxf(m0, __shfl_xor_sync(0xffffffffu, m0, o));
            s1 += __shfl_xor_sync(0xffffffffu, s1, o);
            q1 += __shfl_xor_sync(0xffffffffu, q1, o);
            m1 = fmaxf(m1, __shfl_xor_sync(0xffffffffu, m1, o));
        }
        if ((lane & 3) == 0) {
            atomicAdd(&g_s[r0], s0);
            atomicAdd(&g_s2[r0], q0);
            atomicMax(&g_mxu[r0], fenc(m0));
            atomicAdd(&g_s[r1], s1);
            atomicAdd(&g_s2[r1], q1);
            atomicMax(&g_mxu[r1], fenc(m1));
        }
    }
#undef FILL_STAGE
}

// ---------------- per-row stats -> mu/sc/Mt ----------------
__global__ void k_stats() {
    int i = blockIdx.x * blockDim.x + threadIdx.x;
    if (i >= MR) return;
    double mu = (double)g_s[i] / (double)NN;
    double var = (double)g_s2[i] / (double)NN - mu * mu;
    if (var < 0.0) var = 0.0;
    float sd = (float)fmax(sqrt(var), 1e-30);
    float sc = LAMB_C / sd;
    float mx = fdec(g_mxu[i]);
    g_muv[i] = (float)mu;
    g_scv[i] = sc;
    g_Mtv[i] = sc * (mx - (float)mu);
}

// ---------------- streaming logsumexp (no smem; full occupancy) ----------------
__global__ __launch_bounds__(256) void k_pass() {
    const int i = blockIdx.x;
    const int2 lr = g_lr[i];
    const float pa = g_pos[i & (BB - 1)] + GAMMA_C - g_asq[i];
    const float mu = g_muv[i], sc = g_scv[i], Mt = g_Mtv[i];
    const float* drow = g_dot + (size_t)i * NJ;

    float se = 0.0f;
    for (int j = threadIdx.x; j < NN; j += 256) {
        float fac = 1.0f - (float)(j == lr.x) - (float)(j == lr.y);
        float lv = (pa - g_embsq[j] + 2.0f * drow[j]) * fac;
        float t = sc * (lv - mu) - Mt;
        if (t > -21.0f) se += __expf(t);
    }
    __shared__ double sh[8];
    int lane = threadIdx.x & 31, wid = threadIdx.x >> 5;
    double dse = (double)se;
#pragma unroll
    for (int o = 16; o; o >>= 1) dse += __shfl_xor_sync(0xffffffffu, dse, o);
    if (lane == 0) sh[wid] = dse;
    __syncthreads();
    if (threadIdx.x == 0) {
        double S = 0.0;
        for (int w = 0; w < 8; w++) S += sh[w];
        g_lse[i] = (float)((double)Mt + TAU_C + log(S));
    }
}

// ---------------- final mean ----------------
__global__ void k_final(float* __restrict__ out, int out_size) {
    double s = 0.0;
    for (int i = threadIdx.x; i < MR; i += 256) s += (double)g_lse[i];
    __shared__ double sh[8];
    int lane = threadIdx.x & 31, wid = threadIdx.x >> 5;
#pragma unroll
    for (int o = 16; o; o >>= 1) s += __shfl_xor_sync(0xffffffffu, s, o);
    if (lane == 0) sh[wid] = s;
    __syncthreads();
    if (threadIdx.x == 0) {
        double S = 0.0;
        for (int w = 0; w < 8; w++) S += sh[w];
        float val = (float)(S / (double)BB);
        for (int k = 0; k < out_size; k++) out[k] = val;
    }
}

// ---------------- host launch ----------------
extern "C" void kernel_launch(void* const* d_in, const int* in_sizes, int n_in,
                              void* d_out, int out_size) {
    const int* pairs = (const int*)d_in[0];
    const int* ent_adj = (const int*)d_in[1];
    const int* rel_adj = (const int*)d_in[2];
    const int* adj_list = (const int*)d_in[3];
    const int* r_index = (const int*)d_in[4];
    const float* r_val = (const float*)d_in[5];
    const float* ent_emb = (const float*)d_in[7];
    const float* rel_emb = (const float*)d_in[8];
    const float* attn_e = (const float*)d_in[9];
    const float* attn_r = (const float*)d_in[10];
    float* out = (float*)d_out;

    const int NT = 256;
    const int gb_acc = (int)(((size_t)NN * DD + NT - 1) / NT);
    const int gb_ew = (int)(((size_t)TT * 32 + NT - 1) / NT);
    const int gb_nw = (int)(((size_t)NJ * 32 + NT - 1) / NT);

    k_zero<<<gb_acc, NT>>>();
    k_att<<<gb_ew, NT>>>(r_index + TT, r_val, rel_emb, attn_e, attn_r,
                         ent_adj, rel_adj, adj_list);

    // both GAT chains together
    k_scatter_mean2<<<gb_ew, NT>>>(ent_adj, ent_emb, rel_adj, rel_emb);
    k_finalize_mean2<<<gb_acc, NT>>>();
    for (int l = 0; l < 2; l++) {
        k_reflect2<<<gb_ew, NT>>>(adj_list, l, r_index + TT, r_val, rel_emb);
        k_finalize_tanh2<<<gb_acc, NT>>>(l);
    }

    // align loss
    k_embsq<<<gb_nw, NT>>>();
    k_pairprep<<<BB, NT>>>(pairs);

    const int gemm_smem = 3 * 32768 + 1024;
    cudaFuncSetAttribute(k_gemm_tc, cudaFuncAttributeMaxDynamicSharedMemorySize, gemm_smem);
    dim3 gg(MR / 128, NJ / 128);
    k_gemm_tc<<<gg, 256, gemm_smem>>>();

    k_stats<<<MR / NT, NT>>>();
    k_pass<<<MR, 256>>>();
    k_final<<<1, 256>>>(out, out_size);
}

// round 15
// speedup vs baseline: 2.7156x; 1.0521x over previous
#include <cuda_runtime.h>
#include <cuda_fp16.h>
#include <math.h>
#include <stdint.h>

// Problem constants
#define NN 30000
#define RR 1000
#define TT 200000
#define DD 128
#define BB 2048
#define OD 768
#define NJ 30080
#define MR 4096
#define GAMMA_C 3.0f
#define LAMB_C 30.0f
#define TAU_C 10.0f
#define KCH 12

// ---------------- scratch ----------------
__device__ float g_att[4 * TT];
__device__ float g_acc[(size_t)NN * DD];    // ent chain accumulator
__device__ float g_acc2[(size_t)NN * DD];   // rel chain accumulator
__device__ float g_den[6 * NN];             // [cnt_ent, cnt_rel, z0, z1, z2, z3]
__device__ float g_out[(size_t)NN * OD];
__device__ float g_embsq[NN];
__device__ float g_asq[MR];
__device__ float g_pos[BB];
__device__ int2  g_lr[MR];
__device__ __align__(4) __half g_doth[(size_t)MR * NJ];  // fp16 dot matrix
__device__ float g_lse[MR];
// per-row loss stats (accumulated by GEMM epilogue, fp32 before rounding)
__device__ float g_s[MR];
__device__ float g_s2[MR];
__device__ unsigned g_mxu[MR];
__device__ float g_muv[MR], g_scv[MR], g_Mtv[MR];
// fp16 GEMM operands
__device__ __align__(16) __half g_Ah[(size_t)MR * OD];
__device__ __align__(16) __half g_Bh[(size_t)NJ * OD];

// ---------------- helpers ----------------
__device__ __forceinline__ float warp_sum_f(float v) {
#pragma unroll
    for (int o = 16; o; o >>= 1) v += __shfl_xor_sync(0xffffffffu, v, o);
    return v;
}
__device__ __forceinline__ uint32_t smem_u32(const void* p) {
    uint32_t a;
    asm("{ .reg .u64 t; cvta.to.shared.u64 t, %1; cvt.u32.u64 %0, t; }" : "=r"(a) : "l"(p));
    return a;
}
__device__ __forceinline__ uint32_t swz128(uint32_t b) { return b ^ ((b >> 3) & 0x70); }

__device__ __forceinline__ void cp16(uint32_t dst, const void* src) {
    asm volatile("cp.async.cg.shared.global [%0], [%1], 16;" :: "r"(dst), "l"(src));
}
#define CP_COMMIT() asm volatile("cp.async.commit_group;" ::: "memory")
#define CP_WAIT(n)  asm volatile("cp.async.wait_group %0;" :: "n"(n) : "memory")

__device__ __forceinline__ void ldsm4(uint32_t* r, uint32_t addr) {
    asm volatile("ldmatrix.sync.aligned.m8n8.x4.shared.b16 {%0,%1,%2,%3}, [%4];"
                 : "=r"(r[0]), "=r"(r[1]), "=r"(r[2]), "=r"(r[3]) : "r"(addr));
}
__device__ __forceinline__ void mma_f16(float* c, const uint32_t* a, uint32_t b0, uint32_t b1) {
    asm volatile(
        "mma.sync.aligned.m16n8k16.row.col.f32.f16.f16.f32 "
        "{%0,%1,%2,%3}, {%4,%5,%6,%7}, {%8,%9}, {%0,%1,%2,%3};"
        : "+f"(c[0]), "+f"(c[1]), "+f"(c[2]), "+f"(c[3])
        : "r"(a[0]), "r"(a[1]), "r"(a[2]), "r"(a[3]), "r"(b0), "r"(b1));
}
__device__ __forceinline__ void red4(float* dst, float x, float y, float z, float w) {
    asm volatile("red.global.add.v4.f32 [%0], {%1, %2, %3, %4};"
                 :: "l"(dst), "f"(x), "f"(y), "f"(z), "f"(w) : "memory");
}
// ordered-uint encoding for float atomicMax
__device__ __forceinline__ unsigned fenc(float f) {
    unsigned u = __float_as_uint(f);
    return (u & 0x80000000u) ? ~u : (u | 0x80000000u);
}
__device__ __forceinline__ float fdec(unsigned k) {
    unsigned u = (k & 0x80000000u) ? (k & 0x7FFFFFFFu) : ~k;
    return __uint_as_float(u);
}
// recompute normalized tri_rel row fragment (warp-collective)
__device__ __forceinline__ float4 tri_row(const float* __restrict__ rel_emb,
                                          int rel, float v, int lane) {
    float4 a = ((const float4*)(rel_emb + (size_t)rel * DD))[lane];
    a.x *= v; a.y *= v; a.z *= v; a.w *= v;
    float ss = a.x * a.x + a.y * a.y + a.z * a.z + a.w * a.w;
    ss = warp_sum_f(ss);
    float inv = 1.0f / fmaxf(sqrtf(ss), 1e-12f);
    a.x *= inv; a.y *= inv; a.z *= inv; a.w *= inv;
    return a;
}

// ---------------- zero scratch ----------------
__global__ void k_zero() {
    size_t i = (size_t)blockIdx.x * blockDim.x + threadIdx.x;
    if (i < (size_t)NN * DD) { g_acc[i] = 0.0f; g_acc2[i] = 0.0f; }
    if (i < 6 * NN) g_den[i] = 0.0f;
    if (i < MR) { g_s[i] = 0.0f; g_s2[i] = 0.0f; g_mxu[i] = 0u; }
}

// ---------------- att exps + fused denominators ----------------
__global__ void k_att(const int* __restrict__ r1, const float* __restrict__ rval,
                      const float* __restrict__ rel_emb,
                      const float* __restrict__ attn_e, const float* __restrict__ attn_r,
                      const int* __restrict__ ent_rows, const int* __restrict__ rel_rows,
                      const int* __restrict__ adj_rows) {
    int warp = (int)(((size_t)blockIdx.x * blockDim.x + threadIdx.x) >> 5);
    int lane = threadIdx.x & 31;
    if (warp >= TT) return;
    float4 a = tri_row(rel_emb, r1[warp], rval[warp], lane);

    float4 k0 = ((const float4*)attn_e)[lane];
    float4 k1 = ((const float4*)(attn_e + DD))[lane];
    float4 k2 = ((const float4*)attn_r)[lane];
    float4 k3 = ((const float4*)(attn_r + DD))[lane];
    float d0 = a.x * k0.x + a.y * k0.y + a.z * k0.z + a.w * k0.w;
    float d1 = a.x * k1.x + a.y * k1.y + a.z * k1.z + a.w * k1.w;
    float d2 = a.x * k2.x + a.y * k2.y + a.z * k2.z + a.w * k2.w;
    float d3 = a.x * k3.x + a.y * k3.y + a.z * k3.z + a.w * k3.w;
    d0 = warp_sum_f(d0);
    d1 = warp_sum_f(d1);
    d2 = warp_sum_f(d2);
    d3 = warp_sum_f(d3);
    if (lane == 0) {
        float e0 = expf(d0), e1 = expf(d1), e2 = expf(d2), e3 = expf(d3);
        g_att[0 * TT + warp] = e0;
        g_att[1 * TT + warp] = e1;
        g_att[2 * TT + warp] = e2;
        g_att[3 * TT + warp] = e3;
        atomicAdd(&g_den[ent_rows[warp]], 1.0f);
        atomicAdd(&g_den[NN + rel_rows[warp]], 1.0f);
        int r = adj_rows[warp];
        atomicAdd(&g_den[2 * NN + r], e0);
        atomicAdd(&g_den[3 * NN + r], e1);
        atomicAdd(&g_den[4 * NN + r], e2);
        atomicAdd(&g_den[5 * NN + r], e3);
    }
}

// ---------------- both sparse_mean scatters in one kernel ----------------
__global__ void k_scatter_mean2(const int* __restrict__ ent_adj, const float* __restrict__ ent_emb,
                                const int* __restrict__ rel_adj, const float* __restrict__ rel_emb) {
    int warp = (int)(((size_t)blockIdx.x * blockDim.x + threadIdx.x) >> 5);
    int lane = threadIdx.x & 31;
    if (warp >= TT) return;
    {
        int row = ent_adj[warp];
        int col = ent_adj[TT + warp];
        float4 a = ((const float4*)(ent_emb + (size_t)col * DD))[lane];
        red4(g_acc + (size_t)row * DD + lane * 4, a.x, a.y, a.z, a.w);
    }
    {
        int row = rel_adj[warp];
        int col = rel_adj[TT + warp];
        float4 a = ((const float4*)(rel_emb + (size_t)col * DD))[lane];
        red4(g_acc2 + (size_t)row * DD + lane * 4, a.x, a.y, a.z, a.w);
    }
}

// finalize mean for BOTH chains; zeroes accs; writes g_out + g_Bh only
__global__ void k_finalize_mean2() {
    size_t idx = (size_t)blockIdx.x * blockDim.x + threadIdx.x;
    if (idx >= (size_t)NN * DD) return;
    int n = (int)(idx / DD);
    int d = (int)(idx % DD);
    float ce = fmaxf(g_den[n], 1.0f);
    float cr = fmaxf(g_den[NN + n], 1.0f);
    float fe = tanhf(g_acc[idx] / ce);
    float fr = tanhf(g_acc2[idx] / cr);
    g_acc[idx] = 0.0f;
    g_acc2[idx] = 0.0f;
    size_t oe = (size_t)n * OD + d;
    size_t orr = (size_t)n * OD + 3 * DD + d;
    g_out[oe] = fe;  g_Bh[oe] = __float2half_rn(fe);
    g_out[orr] = fr; g_Bh[orr] = __float2half_rn(fr);
}

// ---------------- dual reflected-neighbor scatter (feats read from g_out blocks) ----------------
__global__ void k_reflect2(const int* __restrict__ adj, int l,
                           const int* __restrict__ r1, const float* __restrict__ rval,
                           const float* __restrict__ rel_emb) {
    int warp = (int)(((size_t)blockIdx.x * blockDim.x + threadIdx.x) >> 5);
    int lane = threadIdx.x & 31;
    if (warp >= TT) return;
    int row = adj[warp];
    int col = adj[TT + warp];
    float we = g_att[l * TT + warp] / g_den[(2 + l) * NN + row];
    float wr = g_att[(2 + l) * TT + warp] / g_den[(4 + l) * NN + row];
    float4 t = tri_row(rel_emb, r1[warp], rval[warp], lane);
    const float* base = g_out + (size_t)col * OD;
    float4 ne = ((const float4*)(base + l * DD))[lane];
    float4 nr = ((const float4*)(base + (3 + l) * DD))[lane];
    float se = ne.x * t.x + ne.y * t.y + ne.z * t.z + ne.w * t.w;
    float sr = nr.x * t.x + nr.y * t.y + nr.z * t.z + nr.w * t.w;
#pragma unroll
    for (int o = 16; o; o >>= 1) {
        se += __shfl_xor_sync(0xffffffffu, se, o);
        sr += __shfl_xor_sync(0xffffffffu, sr, o);
    }
    float ce = 2.0f * se, cr = 2.0f * sr;
    red4(g_acc + (size_t)row * DD + lane * 4,
         we * (ne.x - ce * t.x), we * (ne.y - ce * t.y),
         we * (ne.z - ce * t.z), we * (ne.w - ce * t.w));
    red4(g_acc2 + (size_t)row * DD + lane * 4,
         wr * (nr.x - cr * t.x), wr * (nr.y - cr * t.y),
         wr * (nr.z - cr * t.z), wr * (nr.w - cr * t.w));
}

// finalize tanh for BOTH chains; zeroes accs
__global__ void k_finalize_tanh2(int l) {
    size_t idx = (size_t)blockIdx.x * blockDim.x + threadIdx.x;
    if (idx >= (size_t)NN * DD) return;
    int n = (int)(idx / DD);
    int d = (int)(idx % DD);
    float fe = tanhf(g_acc[idx]);
    float fr = tanhf(g_acc2[idx]);
    g_acc[idx] = 0.0f;
    g_acc2[idx] = 0.0f;
    size_t oe = (size_t)n * OD + (l + 1) * DD + d;
    size_t orr = (size_t)n * OD + (4 + l) * DD + d;
    g_out[oe] = fe;  g_Bh[oe] = __float2half_rn(fe);
    g_out[orr] = fr; g_Bh[orr] = __float2half_rn(fr);
}

// ---------------- row squared norms + zero pad rows of Bh ----------------
__global__ void k_embsq() {
    int row = (int)(((size_t)blockIdx.x * blockDim.x + threadIdx.x) >> 5);
    int lane = threadIdx.x & 31;
    if (row >= NJ) return;
    if (row < NN) {
        const float4* p = (const float4*)(g_out + (size_t)row * OD);
        float ss = 0.0f;
#pragma unroll
        for (int j = lane; j < OD / 4; j += 32) {
            float4 a = p[j];
            ss += a.x * a.x + a.y * a.y + a.z * a.z + a.w * a.w;
        }
        ss = warp_sum_f(ss);
        if (lane == 0) g_embsq[row] = ss;
    } else {
        size_t o = (size_t)row * OD;
        for (int j = lane * 4; j < OD; j += 128) {
#pragma unroll
            for (int q = 0; q < 4; q++) g_Bh[o + j + q] = __float2half_rn(0.0f);
        }
    }
}

// ---------------- gather A (fp16) + pos + asq + lr ----------------
__global__ void k_pairprep(const int* __restrict__ pairs) {
    int i = blockIdx.x;
    int li = pairs[2 * i];
    int ri = pairs[2 * i + 1];
    const float* L = g_out + (size_t)li * OD;
    const float* R = g_out + (size_t)ri * OD;
    float part = 0.0f;
    for (int c = threadIdx.x; c < OD; c += 256) {
        float a = L[c];
        float b = R[c];
        g_Ah[(size_t)i * OD + c] = __float2half_rn(a);
        g_Ah[(size_t)(i + BB) * OD + c] = __float2half_rn(b);
        float d = a - b;
        part += d * d;
    }
    __shared__ float sh[8];
    int lane = threadIdx.x & 31, wid = threadIdx.x >> 5;
    part = warp_sum_f(part);
    if (lane == 0) sh[wid] = part;
    __syncthreads();
    if (threadIdx.x == 0) {
        float s = 0.0f;
        for (int w = 0; w < 8; w++) s += sh[w];
        g_pos[i] = s;
        g_asq[i] = g_embsq[li];
        g_asq[i + BB] = g_embsq[ri];
        g_lr[i] = make_int2(li, ri);
        g_lr[i + BB] = make_int2(li, ri);
    }
}

// ---------------- fp16 GEMM + fused per-row loss stats; fp16 dot output ----------------
__global__ __launch_bounds__(256, 2) void k_gemm_tc() {
    extern __shared__ char smraw[];
    uint32_t sm0 = smem_u32(smraw);
    uint32_t smbase = (sm0 + 1023u) & ~1023u;

    const int tid = threadIdx.x;
    const int warp = tid >> 5;
    const int lane = tid & 31;
    const int bi = blockIdx.x;
    const int bj = blockIdx.y;

    const uint4* srcs[2];
    srcs[0] = (const uint4*)g_Ah + (size_t)(bi * 128) * 96;
    srcs[1] = (const uint4*)g_Bh + (size_t)(bj * 128) * 96;

    const int frow = tid >> 3;
    const int fc = tid & 7;
#define FILL_STAGE(kc, stage)                                                    \
    do {                                                                         \
        uint32_t st_ = smbase + (uint32_t)(stage) * 32768u;                      \
        _Pragma("unroll")                                                        \
        for (int m_ = 0; m_ < 2; m_++) {                                         \
            const uint4* src_ = srcs[m_];                                        \
            uint32_t tb_ = st_ + m_ * 16384u;                                    \
            _Pragma("unroll")                                                    \
            for (int i_ = 0; i_ < 4; i_++) {                                     \
                int row_ = frow + i_ * 32;                                       \
                cp16(tb_ + swz128((uint32_t)(row_ * 128 + fc * 16)),             \
                     src_ + (size_t)row_ * 96 + (kc) * 8 + fc);                  \
            }                                                                    \
        }                                                                        \
        CP_COMMIT();                                                             \
    } while (0)

    const int wm = warp >> 2;
    const int wn = warp & 3;
    uint32_t mrow[4], brow[2];
#pragma unroll
    for (int mi = 0; mi < 4; mi++)
        mrow[mi] = (uint32_t)((wm * 64 + mi * 16 + (lane & 15)) * 128);
#pragma unroll
    for (int g = 0; g < 2; g++)
        brow[g] = (uint32_t)((wn * 32 + g * 16 + (lane & 7) + ((lane >> 3) & 1) * 8) * 128);
    const uint32_t csel = (uint32_t)(((lane >> 4) & 1) * 16);

    float acc[4][4][4];
#pragma unroll
    for (int mi = 0; mi < 4; mi++)
#pragma unroll
        for (int nj = 0; nj < 4; nj++)
#pragma unroll
            for (int q = 0; q < 4; q++) acc[mi][nj][q] = 0.0f;

    FILL_STAGE(0, 0);
    FILL_STAGE(1, 1);

    for (int k = 0; k < KCH; k++) {
        if (k + 1 < KCH) CP_WAIT(1);
        else CP_WAIT(0);
        __syncthreads();
        if (k + 2 < KCH) FILL_STAGE(k + 2, (k + 2) % 3);

        int s = k % 3;
        uint32_t Ahb = smbase + (uint32_t)s * 32768u;
        uint32_t Bhb = Ahb + 16384u;
#pragma unroll
        for (int ks = 0; ks < 4; ks++) {
            uint32_t col = (uint32_t)(ks * 32) + csel;
            uint32_t ah[4][4], bh[2][4];
#pragma unroll
            for (int mi = 0; mi < 4; mi++) ldsm4(ah[mi], Ahb + swz128(mrow[mi] + col));
#pragma unroll
            for (int g = 0; g < 2; g++) ldsm4(bh[g], Bhb + swz128(brow[g] + col));
#pragma unroll
            for (int mi = 0; mi < 4; mi++) {
#pragma unroll
                for (int nj = 0; nj < 4; nj++) {
                    int g = nj >> 1, h = nj & 1;
                    mma_f16(acc[mi][nj], ah[mi], bh[g][h], bh[g][h + 2]);
                }
            }
        }
    }

    // epilogue: write fp16 dot + accumulate per-row fp32 loss stats
    const int mrow0 = bi * 128 + wm * 64;
    const int ncol0 = bj * 128 + wn * 32;
    const int rofs = lane >> 2;
    const int cofs = (lane & 3) * 2;
#pragma unroll
    for (int mi = 0; mi < 4; mi++) {
        int r0 = mrow0 + mi * 16 + rofs;
        int r1 = r0 + 8;
        int2 lr0 = g_lr[r0];
        int2 lr1 = g_lr[r1];
        float pa0 = g_pos[r0 & (BB - 1)] + GAMMA_C - g_asq[r0];
        float pa1 = g_pos[r1 & (BB - 1)] + GAMMA_C - g_asq[r1];
        float s0 = 0.0f, q0 = 0.0f, m0 = -3.4e38f;
        float s1 = 0.0f, q1 = 0.0f, m1 = -3.4e38f;
#pragma unroll
        for (int nj = 0; nj < 4; nj++) {
            int cbase = ncol0 + nj * 8 + cofs;
            size_t c0 = (size_t)cbase;
            *(__half2*)(g_doth + (size_t)r0 * NJ + c0) =
                __floats2half2_rn(acc[mi][nj][0], acc[mi][nj][1]);
            *(__half2*)(g_doth + (size_t)r1 * NJ + c0) =
                __floats2half2_rn(acc[mi][nj][2], acc[mi][nj][3]);
#pragma unroll
            for (int q = 0; q < 2; q++) {
                int j = cbase + q;
                if (j < NN) {
                    float e = g_embsq[j];
                    float fac0 = 1.0f - (float)(j == lr0.x) - (float)(j == lr0.y);
                    float lv0 = (pa0 - e + 2.0f * acc[mi][nj][q]) * fac0;
                    s0 += lv0; q0 = fmaf(lv0, lv0, q0); m0 = fmaxf(m0, lv0);
                    float fac1 = 1.0f - (float)(j == lr1.x) - (float)(j == lr1.y);
                    float lv1 = (pa1 - e + 2.0f * acc[mi][nj][2 + q]) * fac1;
                    s1 += lv1; q1 = fmaf(lv1, lv1, q1); m1 = fmaxf(m1, lv1);
                }
            }
        }
#pragma unroll
        for (int o = 1; o <= 2; o <<= 1) {
            s0 += __shfl_xor_sync(0xffffffffu, s0, o);
            q0 += __shfl_xor_sync(0xffffffffu, q0, o);
            m0 = fmaxf(m0, __shfl_xor_sync(0xffffffffu, m0, o));
            s1 += __shfl_xor_sync(0xffffffffu, s1, o);
            q1 += __shfl_xor_sync(0xffffffffu, q1, o);
            m1 = fmaxf(m1, __shfl_xor_sync(0xffffffffu, m1, o));
        }
        if ((lane & 3) == 0) {
            atomicAdd(&g_s[r0], s0);
            atomicAdd(&g_s2[r0], q0);
            atomicMax(&g_mxu[r0], fenc(m0));
            atomicAdd(&g_s[r1], s1);
            atomicAdd(&g_s2[r1], q1);
            atomicMax(&g_mxu[r1], fenc(m1));
        }
    }
#undef FILL_STAGE
}

// ---------------- per-row stats -> mu/sc/Mt ----------------
__global__ void k_stats() {
    int i = blockIdx.x * blockDim.x + threadIdx.x;
    if (i >= MR) return;
    double mu = (double)g_s[i] / (double)NN;
    double var = (double)g_s2[i] / (double)NN - mu * mu;
    if (var < 0.0) var = 0.0;
    float sd = (float)fmax(sqrt(var), 1e-30);
    float sc = LAMB_C / sd;
    float mx = fdec(g_mxu[i]);
    g_muv[i] = (float)mu;
    g_scv[i] = sc;
    g_Mtv[i] = sc * (mx - (float)mu);
}

// ---------------- streaming logsumexp over fp16 dot ----------------
__global__ __launch_bounds__(256) void k_pass() {
    const int i = blockIdx.x;
    const int2 lr = g_lr[i];
    const float pa = g_pos[i & (BB - 1)] + GAMMA_C - g_asq[i];
    const float mu = g_muv[i], sc = g_scv[i], Mt = g_Mtv[i];
    const __half2* drow = (const __half2*)(g_doth + (size_t)i * NJ);

    float se = 0.0f;
    for (int j2 = threadIdx.x; j2 < NN / 2; j2 += 256) {
        float2 d = __half22float2(drow[j2]);
        int j = 2 * j2;
        float fac0 = 1.0f - (float)(j == lr.x) - (float)(j == lr.y);
        float lv0 = (pa - g_embsq[j] + 2.0f * d.x) * fac0;
        float t0 = sc * (lv0 - mu) - Mt;
        if (t0 > -21.0f) se += __expf(t0);
        int j1 = j + 1;
        float fac1 = 1.0f - (float)(j1 == lr.x) - (float)(j1 == lr.y);
        float lv1 = (pa - g_embsq[j1] + 2.0f * d.y) * fac1;
        float t1 = sc * (lv1 - mu) - Mt;
        if (t1 > -21.0f) se += __expf(t1);
    }
    __shared__ double sh[8];
    int lane = threadIdx.x & 31, wid = threadIdx.x >> 5;
    double dse = (double)se;
#pragma unroll
    for (int o = 16; o; o >>= 1) dse += __shfl_xor_sync(0xffffffffu, dse, o);
    if (lane == 0) sh[wid] = dse;
    __syncthreads();
    if (threadIdx.x == 0) {
        double S = 0.0;
        for (int w = 0; w < 8; w++) S += sh[w];
        g_lse[i] = (float)((double)Mt + TAU_C + log(S));
    }
}

// ---------------- final mean ----------------
__global__ void k_final(float* __restrict__ out, int out_size) {
    double s = 0.0;
    for (int i = threadIdx.x; i < MR; i += 256) s += (double)g_lse[i];
    __shared__ double sh[8];
    int lane = threadIdx.x & 31, wid = threadIdx.x >> 5;
#pragma unroll
    for (int o = 16; o; o >>= 1) s += __shfl_xor_sync(0xffffffffu, s, o);
    if (lane == 0) sh[wid] = s;
    __syncthreads();
    if (threadIdx.x == 0) {
        double S = 0.0;
        for (int w = 0; w < 8; w++) S += sh[w];
        float val = (float)(S / (double)BB);
        for (int k = 0; k < out_size; k++) out[k] = val;
    }
}

// ---------------- host launch ----------------
extern "C" void kernel_launch(void* const* d_in, const int* in_sizes, int n_in,
                              void* d_out, int out_size) {
    const int* pairs = (const int*)d_in[0];
    const int* ent_adj = (const int*)d_in[1];
    const int* rel_adj = (const int*)d_in[2];
    const int* adj_list = (const int*)d_in[3];
    const int* r_index = (const int*)d_in[4];
    const float* r_val = (const float*)d_in[5];
    const float* ent_emb = (const float*)d_in[7];
    const float* rel_emb = (const float*)d_in[8];
    const float* attn_e = (const float*)d_in[9];
    const float* attn_r = (const float*)d_in[10];
    float* out = (float*)d_out;

    const int NT = 256;
    const int gb_acc = (int)(((size_t)NN * DD + NT - 1) / NT);
    const int gb_ew = (int)(((size_t)TT * 32 + NT - 1) / NT);
    const int gb_nw = (int)(((size_t)NJ * 32 + NT - 1) / NT);

    k_zero<<<gb_acc, NT>>>();
    k_att<<<gb_ew, NT>>>(r_index + TT, r_val, rel_emb, attn_e, attn_r,
                         ent_adj, rel_adj, adj_list);

    // both GAT chains together
    k_scatter_mean2<<<gb_ew, NT>>>(ent_adj, ent_emb, rel_adj, rel_emb);
    k_finalize_mean2<<<gb_acc, NT>>>();
    for (int l = 0; l < 2; l++) {
        k_reflect2<<<gb_ew, NT>>>(adj_list, l, r_index + TT, r_val, rel_emb);
        k_finalize_tanh2<<<gb_acc, NT>>>(l);
    }

    // align loss
    k_embsq<<<gb_nw, NT>>>();
    k_pairprep<<<BB, NT>>>(pairs);

    const int gemm_smem = 3 * 32768 + 1024;
    cudaFuncSetAttribute(k_gemm_tc, cudaFuncAttributeMaxDynamicSharedMemorySize, gemm_smem);
    dim3 gg(MR / 128, NJ / 128);
    k_gemm_tc<<<gg, 256, gemm_smem>>>();

    k_stats<<<MR / NT, NT>>>();
    k_pass<<<MR, 256>>>();
    k_final<<<1, 256>>>(out, out_size);
}

// round 16
// speedup vs baseline: 2.8303x; 1.0422x over previous
#include <cuda_runtime.h>
#include <cuda_fp16.h>
#include <math.h>
#include <stdint.h>

// Problem constants
#define NN 30000
#define RR 1000
#define TT 200000
#define DD 128
#define BB 2048
#define OD 768
#define NJ 30080
#define MR 4096
#define GAMMA_C 3.0f
#define LAMB_C 30.0f
#define TAU_C 10.0f
#define KCH 12

// ---------------- scratch ----------------
__device__ float g_att[4 * TT];
__device__ float g_acc[(size_t)NN * DD];
__device__ float g_acc2[(size_t)NN * DD];
__device__ float g_den[6 * NN];             // [cnt_ent, cnt_rel, z0, z1, z2, z3]
__device__ float g_embsq[NN];
__device__ float g_asq[MR];
__device__ float g_pos[BB];
__device__ int2  g_lr[MR];
__device__ __align__(4) __half g_doth[(size_t)MR * NJ];
__device__ float g_lse[MR];
// per-row loss stats
__device__ float g_s[MR];
__device__ float g_s2[MR];
__device__ unsigned g_mxu[MR];
// fp16 embedding (single source of truth) + A operand
__device__ __align__(16) __half g_Bh[(size_t)NJ * OD];
__device__ __align__(16) __half g_Ah[(size_t)MR * OD];

// ---------------- helpers ----------------
__device__ __forceinline__ float warp_sum_f(float v) {
#pragma unroll
    for (int o = 16; o; o >>= 1) v += __shfl_xor_sync(0xffffffffu, v, o);
    return v;
}
__device__ __forceinline__ uint32_t smem_u32(const void* p) {
    uint32_t a;
    asm("{ .reg .u64 t; cvta.to.shared.u64 t, %1; cvt.u32.u64 %0, t; }" : "=r"(a) : "l"(p));
    return a;
}
__device__ __forceinline__ uint32_t swz128(uint32_t b) { return b ^ ((b >> 3) & 0x70); }

__device__ __forceinline__ void cp16(uint32_t dst, const void* src) {
    asm volatile("cp.async.cg.shared.global [%0], [%1], 16;" :: "r"(dst), "l"(src));
}
#define CP_COMMIT() asm volatile("cp.async.commit_group;" ::: "memory")
#define CP_WAIT(n)  asm volatile("cp.async.wait_group %0;" :: "n"(n) : "memory")

__device__ __forceinline__ void ldsm4(uint32_t* r, uint32_t addr) {
    asm volatile("ldmatrix.sync.aligned.m8n8.x4.shared.b16 {%0,%1,%2,%3}, [%4];"
                 : "=r"(r[0]), "=r"(r[1]), "=r"(r[2]), "=r"(r[3]) : "r"(addr));
}
__device__ __forceinline__ void mma_f16(float* c, const uint32_t* a, uint32_t b0, uint32_t b1) {
    asm volatile(
        "mma.sync.aligned.m16n8k16.row.col.f32.f16.f16.f32 "
        "{%0,%1,%2,%3}, {%4,%5,%6,%7}, {%8,%9}, {%0,%1,%2,%3};"
        : "+f"(c[0]), "+f"(c[1]), "+f"(c[2]), "+f"(c[3])
        : "r"(a[0]), "r"(a[1]), "r"(a[2]), "r"(a[3]), "r"(b0), "r"(b1));
}
__device__ __forceinline__ void red4(float* dst, float x, float y, float z, float w) {
    asm volatile("red.global.add.v4.f32 [%0], {%1, %2, %3, %4};"
                 :: "l"(dst), "f"(x), "f"(y), "f"(z), "f"(w) : "memory");
}
__device__ __forceinline__ unsigned fenc(float f) {
    unsigned u = __float_as_uint(f);
    return (u & 0x80000000u) ? ~u : (u | 0x80000000u);
}
__device__ __forceinline__ float fdec(unsigned k) {
    unsigned u = (k & 0x80000000u) ? (k & 0x7FFFFFFFu) : ~k;
    return __uint_as_float(u);
}
// recompute normalized tri_rel row fragment (warp-collective)
__device__ __forceinline__ float4 tri_row(const float* __restrict__ rel_emb,
                                          int rel, float v, int lane) {
    float4 a = ((const float4*)(rel_emb + (size_t)rel * DD))[lane];
    a.x *= v; a.y *= v; a.z *= v; a.w *= v;
    float ss = a.x * a.x + a.y * a.y + a.z * a.z + a.w * a.w;
    ss = warp_sum_f(ss);
    float inv = 1.0f / fmaxf(sqrtf(ss), 1e-12f);
    a.x *= inv; a.y *= inv; a.z *= inv; a.w *= inv;
    return a;
}
// load 4 consecutive halves -> float4 (8B load)
__device__ __forceinline__ float4 ldh4(const __half* p) {
    uint2 u = *(const uint2*)p;
    float2 lo = __half22float2(*(__half2*)&u.x);
    float2 hi = __half22float2(*(__half2*)&u.y);
    return make_float4(lo.x, lo.y, hi.x, hi.y);
}

// ---------------- zero scratch ----------------
__global__ void k_zero() {
    size_t i = (size_t)blockIdx.x * blockDim.x + threadIdx.x;
    if (i < (size_t)NN * DD) { g_acc[i] = 0.0f; g_acc2[i] = 0.0f; }
    if (i < 6 * NN) g_den[i] = 0.0f;
    if (i < MR) { g_s[i] = 0.0f; g_s2[i] = 0.0f; g_mxu[i] = 0u; }
}

// ---------------- att exps + denominators + BOTH sparse_mean scatters ----------------
__global__ void k_att_scatter(const int* __restrict__ r1, const float* __restrict__ rval,
                              const float* __restrict__ rel_emb,
                              const float* __restrict__ attn_e, const float* __restrict__ attn_r,
                              const int* __restrict__ ent_adj, const float* __restrict__ ent_emb,
                              const int* __restrict__ rel_adj) {
    int warp = (int)(((size_t)blockIdx.x * blockDim.x + threadIdx.x) >> 5);
    int lane = threadIdx.x & 31;
    if (warp >= TT) return;
    float4 a = tri_row(rel_emb, r1[warp], rval[warp], lane);

    float4 k0 = ((const float4*)attn_e)[lane];
    float4 k1 = ((const float4*)(attn_e + DD))[lane];
    float4 k2 = ((const float4*)attn_r)[lane];
    float4 k3 = ((const float4*)(attn_r + DD))[lane];
    float d0 = a.x * k0.x + a.y * k0.y + a.z * k0.z + a.w * k0.w;
    float d1 = a.x * k1.x + a.y * k1.y + a.z * k1.z + a.w * k1.w;
    float d2 = a.x * k2.x + a.y * k2.y + a.z * k2.z + a.w * k2.w;
    float d3 = a.x * k3.x + a.y * k3.y + a.z * k3.z + a.w * k3.w;
    d0 = warp_sum_f(d0);
    d1 = warp_sum_f(d1);
    d2 = warp_sum_f(d2);
    d3 = warp_sum_f(d3);
    int adjrow = ent_adj[warp];  // reused below for scatter
    if (lane == 0) {
        float e0 = expf(d0), e1 = expf(d1), e2 = expf(d2), e3 = expf(d3);
        g_att[0 * TT + warp] = e0;
        g_att[1 * TT + warp] = e1;
        g_att[2 * TT + warp] = e2;
        g_att[3 * TT + warp] = e3;
        atomicAdd(&g_den[adjrow], 1.0f);
        atomicAdd(&g_den[NN + rel_adj[warp]], 1.0f);
        // softmax z uses adj_list rows == r1's companion; pass adj rows via rel? no:
    }
    // scatter means
    {
        int col = ent_adj[TT + warp];
        float4 v = ((const float4*)(ent_emb + (size_t)col * DD))[lane];
        red4(g_acc + (size_t)adjrow * DD + lane * 4, v.x, v.y, v.z, v.w);
    }
    {
        int row = rel_adj[warp];
        int col = rel_adj[TT + warp];
        float4 v = ((const float4*)(rel_emb + (size_t)col * DD))[lane];
        red4(g_acc2 + (size_t)row * DD + lane * 4, v.x, v.y, v.z, v.w);
    }
}

// softmax z denominators over adj_list rows (separate tiny kernel; thread per edge)
__global__ void k_zden(const int* __restrict__ adj_rows) {
    int e = blockIdx.x * blockDim.x + threadIdx.x;
    if (e >= TT) return;
    int r = adj_rows[e];
    atomicAdd(&g_den[2 * NN + r], g_att[0 * TT + e]);
    atomicAdd(&g_den[3 * NN + r], g_att[1 * TT + e]);
    atomicAdd(&g_den[4 * NN + r], g_att[2 * TT + e]);
    atomicAdd(&g_den[5 * NN + r], g_att[3 * TT + e]);
}

// finalize mean for BOTH chains; zeroes accs; writes fp16 g_Bh blocks 0 and 3
__global__ void k_finalize_mean2() {
    size_t idx = (size_t)blockIdx.x * blockDim.x + threadIdx.x;
    if (idx >= (size_t)NN * DD) return;
    int n = (int)(idx / DD);
    int d = (int)(idx % DD);
    float ce = fmaxf(g_den[n], 1.0f);
    float cr = fmaxf(g_den[NN + n], 1.0f);
    float fe = tanhf(g_acc[idx] / ce);
    float fr = tanhf(g_acc2[idx] / cr);
    g_acc[idx] = 0.0f;
    g_acc2[idx] = 0.0f;
    g_Bh[(size_t)n * OD + d] = __float2half_rn(fe);
    g_Bh[(size_t)n * OD + 3 * DD + d] = __float2half_rn(fr);
}

// ---------------- dual reflected-neighbor scatter (fp16 feats from g_Bh) ----------------
__global__ void k_reflect2(const int* __restrict__ adj, int l,
                           const int* __restrict__ r1, const float* __restrict__ rval,
                           const float* __restrict__ rel_emb) {
    int warp = (int)(((size_t)blockIdx.x * blockDim.x + threadIdx.x) >> 5);
    int lane = threadIdx.x & 31;
    if (warp >= TT) return;
    int row = adj[warp];
    int col = adj[TT + warp];
    float we = g_att[l * TT + warp] / g_den[(2 + l) * NN + row];
    float wr = g_att[(2 + l) * TT + warp] / g_den[(4 + l) * NN + row];
    float4 t = tri_row(rel_emb, r1[warp], rval[warp], lane);
    const __half* base = g_Bh + (size_t)col * OD;
    float4 ne = ldh4(base + l * DD + lane * 4);
    float4 nr = ldh4(base + (3 + l) * DD + lane * 4);
    float se = ne.x * t.x + ne.y * t.y + ne.z * t.z + ne.w * t.w;
    float sr = nr.x * t.x + nr.y * t.y + nr.z * t.z + nr.w * t.w;
#pragma unroll
    for (int o = 16; o; o >>= 1) {
        se += __shfl_xor_sync(0xffffffffu, se, o);
        sr += __shfl_xor_sync(0xffffffffu, sr, o);
    }
    float ce = 2.0f * se, cr = 2.0f * sr;
    red4(g_acc + (size_t)row * DD + lane * 4,
         we * (ne.x - ce * t.x), we * (ne.y - ce * t.y),
         we * (ne.z - ce * t.z), we * (ne.w - ce * t.w));
    red4(g_acc2 + (size_t)row * DD + lane * 4,
         wr * (nr.x - cr * t.x), wr * (nr.y - cr * t.y),
         wr * (nr.z - cr * t.z), wr * (nr.w - cr * t.w));
}

// finalize tanh for BOTH chains; zeroes accs; fp16 out
__global__ void k_finalize_tanh2(int l) {
    size_t idx = (size_t)blockIdx.x * blockDim.x + threadIdx.x;
    if (idx >= (size_t)NN * DD) return;
    int n = (int)(idx / DD);
    int d = (int)(idx % DD);
    float fe = tanhf(g_acc[idx]);
    float fr = tanhf(g_acc2[idx]);
    g_acc[idx] = 0.0f;
    g_acc2[idx] = 0.0f;
    g_Bh[(size_t)n * OD + (l + 1) * DD + d] = __float2half_rn(fe);
    g_Bh[(size_t)n * OD + (4 + l) * DD + d] = __float2half_rn(fr);
}

// ---------------- prep: pairprep (blocks 0..BB-1) + embsq/pad (blocks BB..) ----------------
__global__ void k_prep(const int* __restrict__ pairs) {
    if (blockIdx.x < BB) {
        int i = blockIdx.x;
        int li = pairs[2 * i];
        int ri = pairs[2 * i + 1];
        const __half* L = g_Bh + (size_t)li * OD;
        const __half* R = g_Bh + (size_t)ri * OD;
        float pd = 0.0f, pa = 0.0f, pb = 0.0f;
        for (int c = threadIdx.x; c < OD; c += 256) {
            __half ha = L[c];
            __half hb = R[c];
            g_Ah[(size_t)i * OD + c] = ha;
            g_Ah[(size_t)(i + BB) * OD + c] = hb;
            float a = __half2float(ha);
            float b = __half2float(hb);
            float d = a - b;
            pd += d * d;
            pa += a * a;
            pb += b * b;
        }
        __shared__ float sh[3][8];
        int lane = threadIdx.x & 31, wid = threadIdx.x >> 5;
        pd = warp_sum_f(pd);
        pa = warp_sum_f(pa);
        pb = warp_sum_f(pb);
        if (lane == 0) { sh[0][wid] = pd; sh[1][wid] = pa; sh[2][wid] = pb; }
        __syncthreads();
        if (threadIdx.x == 0) {
            float sd = 0.0f, sa = 0.0f, sb = 0.0f;
            for (int w = 0; w < 8; w++) { sd += sh[0][w]; sa += sh[1][w]; sb += sh[2][w]; }
            g_pos[i] = sd;
            g_asq[i] = sa;
            g_asq[i + BB] = sb;
            g_lr[i] = make_int2(li, ri);
            g_lr[i + BB] = make_int2(li, ri);
        }
    } else {
        int row = (int)((blockIdx.x - BB) * 8 + (threadIdx.x >> 5));
        int lane = threadIdx.x & 31;
        if (row >= NJ) return;
        if (row < NN) {
            const __half* p = g_Bh + (size_t)row * OD;
            float ss = 0.0f;
#pragma unroll
            for (int j = lane; j < OD / 4; j += 32) {
                float4 a = ldh4(p + j * 4);
                ss += a.x * a.x + a.y * a.y + a.z * a.z + a.w * a.w;
            }
            ss = warp_sum_f(ss);
            if (lane == 0) g_embsq[row] = ss;
        } else {
            __half2 z = __floats2half2_rn(0.0f, 0.0f);
            __half2* o = (__half2*)(g_Bh + (size_t)row * OD);
            for (int j = lane; j < OD / 2; j += 32) o[j] = z;
        }
    }
}

// ---------------- fp16 GEMM + fused per-row loss stats; fp16 dot output ----------------
__global__ __launch_bounds__(256, 2) void k_gemm_tc() {
    extern __shared__ char smraw[];
    uint32_t sm0 = smem_u32(smraw);
    uint32_t smbase = (sm0 + 1023u) & ~1023u;

    const int tid = threadIdx.x;
    const int warp = tid >> 5;
    const int lane = tid & 31;
    const int bi = blockIdx.x;
    const int bj = blockIdx.y;

    const uint4* srcs[2];
    srcs[0] = (const uint4*)g_Ah + (size_t)(bi * 128) * 96;
    srcs[1] = (const uint4*)g_Bh + (size_t)(bj * 128) * 96;

    const int frow = tid >> 3;
    const int fc = tid & 7;
#define FILL_STAGE(kc, stage)                                                    \
    do {                                                                         \
        uint32_t st_ = smbase + (uint32_t)(stage) * 32768u;                      \
        _Pragma("unroll")                                                        \
        for (int m_ = 0; m_ < 2; m_++) {                                         \
            const uint4* src_ = srcs[m_];                                        \
            uint32_t tb_ = st_ + m_ * 16384u;                                    \
            _Pragma("unroll")                                                    \
            for (int i_ = 0; i_ < 4; i_++) {                                     \
                int row_ = frow + i_ * 32;                                       \
                cp16(tb_ + swz128((uint32_t)(row_ * 128 + fc * 16)),             \
                     src_ + (size_t)row_ * 96 + (kc) * 8 + fc);                  \
            }                                                                    \
        }                                                                        \
        CP_COMMIT();                                                             \
    } while (0)

    const int wm = warp >> 2;
    const int wn = warp & 3;
    uint32_t mrow[4], brow[2];
#pragma unroll
    for (int mi = 0; mi < 4; mi++)
        mrow[mi] = (uint32_t)((wm * 64 + mi * 16 + (lane & 15)) * 128);
#pragma unroll
    for (int g = 0; g < 2; g++)
        brow[g] = (uint32_t)((wn * 32 + g * 16 + (lane & 7) + ((lane >> 3) & 1) * 8) * 128);
    const uint32_t csel = (uint32_t)(((lane >> 4) & 1) * 16);

    float acc[4][4][4];
#pragma unroll
    for (int mi = 0; mi < 4; mi++)
#pragma unroll
        for (int nj = 0; nj < 4; nj++)
#pragma unroll
            for (int q = 0; q < 4; q++) acc[mi][nj][q] = 0.0f;

    FILL_STAGE(0, 0);
    FILL_STAGE(1, 1);

    for (int k = 0; k < KCH; k++) {
        if (k + 1 < KCH) CP_WAIT(1);
        else CP_WAIT(0);
        __syncthreads();
        if (k + 2 < KCH) FILL_STAGE(k + 2, (k + 2) % 3);

        int s = k % 3;
        uint32_t Ahb = smbase + (uint32_t)s * 32768u;
        uint32_t Bhb = Ahb + 16384u;
#pragma unroll
        for (int ks = 0; ks < 4; ks++) {
            uint32_t col = (uint32_t)(ks * 32) + csel;
            uint32_t ah[4][4], bh[2][4];
#pragma unroll
            for (int mi = 0; mi < 4; mi++) ldsm4(ah[mi], Ahb + swz128(mrow[mi] + col));
#pragma unroll
            for (int g = 0; g < 2; g++) ldsm4(bh[g], Bhb + swz128(brow[g] + col));
#pragma unroll
            for (int mi = 0; mi < 4; mi++) {
#pragma unroll
                for (int nj = 0; nj < 4; nj++) {
                    int g = nj >> 1, h = nj & 1;
                    mma_f16(acc[mi][nj], ah[mi], bh[g][h], bh[g][h + 2]);
                }
            }
        }
    }

    // epilogue
    const int mrow0 = bi * 128 + wm * 64;
    const int ncol0 = bj * 128 + wn * 32;
    const int rofs = lane >> 2;
    const int cofs = (lane & 3) * 2;
#pragma unroll
    for (int mi = 0; mi < 4; mi++) {
        int r0 = mrow0 + mi * 16 + rofs;
        int r1 = r0 + 8;
        int2 lr0 = g_lr[r0];
        int2 lr1 = g_lr[r1];
        float pa0 = g_pos[r0 & (BB - 1)] + GAMMA_C - g_asq[r0];
        float pa1 = g_pos[r1 & (BB - 1)] + GAMMA_C - g_asq[r1];
        float s0 = 0.0f, q0 = 0.0f, m0 = -3.4e38f;
        float s1 = 0.0f, q1 = 0.0f, m1 = -3.4e38f;
#pragma unroll
        for (int nj = 0; nj < 4; nj++) {
            int cbase = ncol0 + nj * 8 + cofs;
            size_t c0 = (size_t)cbase;
            *(__half2*)(g_doth + (size_t)r0 * NJ + c0) =
                __floats2half2_rn(acc[mi][nj][0], acc[mi][nj][1]);
            *(__half2*)(g_doth + (size_t)r1 * NJ + c0) =
                __floats2half2_rn(acc[mi][nj][2], acc[mi][nj][3]);
#pragma unroll
            for (int q = 0; q < 2; q++) {
                int j = cbase + q;
                if (j < NN) {
                    float e = g_embsq[j];
                    float fac0 = 1.0f - (float)(j == lr0.x) - (float)(j == lr0.y);
                    float lv0 = (pa0 - e + 2.0f * acc[mi][nj][q]) * fac0;
                    s0 += lv0; q0 = fmaf(lv0, lv0, q0); m0 = fmaxf(m0, lv0);
                    float fac1 = 1.0f - (float)(j == lr1.x) - (float)(j == lr1.y);
                    float lv1 = (pa1 - e + 2.0f * acc[mi][nj][2 + q]) * fac1;
                    s1 += lv1; q1 = fmaf(lv1, lv1, q1); m1 = fmaxf(m1, lv1);
                }
            }
        }
#pragma unroll
        for (int o = 1; o <= 2; o <<= 1) {
            s0 += __shfl_xor_sync(0xffffffffu, s0, o);
            q0 += __shfl_xor_sync(0xffffffffu, q0, o);
            m0 = fmaxf(m0, __shfl_xor_sync(0xffffffffu, m0, o));
            s1 += __shfl_xor_sync(0xffffffffu, s1, o);
            q1 += __shfl_xor_sync(0xffffffffu, q1, o);
            m1 = fmaxf(m1, __shfl_xor_sync(0xffffffffu, m1, o));
        }
        if ((lane & 3) == 0) {
            atomicAdd(&g_s[r0], s0);
            atomicAdd(&g_s2[r0], q0);
            atomicMax(&g_mxu[r0], fenc(m0));
            atomicAdd(&g_s[r1], s1);
            atomicAdd(&g_s2[r1], q1);
            atomicMax(&g_mxu[r1], fenc(m1));
        }
    }
#undef FILL_STAGE
}

// ---------------- streaming logsumexp over fp16 dot (stats derived inline) ----------------
__global__ __launch_bounds__(256) void k_pass() {
    const int i = blockIdx.x;
    const int2 lr = g_lr[i];
    const float pa = g_pos[i & (BB - 1)] + GAMMA_C - g_asq[i];
    // derive per-row stats (all threads redundantly; cheap)
    double mud = (double)g_s[i] / (double)NN;
    double var = (double)g_s2[i] / (double)NN - mud * mud;
    if (var < 0.0) var = 0.0;
    float sd = (float)fmax(sqrt(var), 1e-30);
    const float sc = LAMB_C / sd;
    const float mu = (float)mud;
    const float Mt = sc * (fdec(g_mxu[i]) - mu);

    const uint4* drow = (const uint4*)(g_doth + (size_t)i * NJ);
    float se = 0.0f;
    for (int j8 = threadIdx.x; j8 < NN / 8; j8 += 256) {
        uint4 u = drow[j8];
        float2 d01 = __half22float2(*(__half2*)&u.x);
        float2 d23 = __half22float2(*(__half2*)&u.y);
        float2 d45 = __half22float2(*(__half2*)&u.z);
        float2 d67 = __half22float2(*(__half2*)&u.w);
        float dv[8] = {d01.x, d01.y, d23.x, d23.y, d45.x, d45.y, d67.x, d67.y};
        int jb = j8 * 8;
#pragma unroll
        for (int q = 0; q < 8; q++) {
            int j = jb + q;
            float fac = 1.0f - (float)(j == lr.x) - (float)(j == lr.y);
            float lv = (pa - g_embsq[j] + 2.0f * dv[q]) * fac;
            float t = sc * (lv - mu) - Mt;
            if (t > -21.0f) se += __expf(t);
        }
    }
    __shared__ double sh[8];
    int lane = threadIdx.x & 31, wid = threadIdx.x >> 5;
    double dse = (double)se;
#pragma unroll
    for (int o = 16; o; o >>= 1) dse += __shfl_xor_sync(0xffffffffu, dse, o);
    if (lane == 0) sh[wid] = dse;
    __syncthreads();
    if (threadIdx.x == 0) {
        double S = 0.0;
        for (int w = 0; w < 8; w++) S += sh[w];
        g_lse[i] = (float)((double)Mt + TAU_C + log(S));
    }
}

// ---------------- final mean ----------------
__global__ void k_final(float* __restrict__ out, int out_size) {
    double s = 0.0;
    for (int i = threadIdx.x; i < MR; i += 256) s += (double)g_lse[i];
    __shared__ double sh[8];
    int lane = threadIdx.x & 31, wid = threadIdx.x >> 5;
#pragma unroll
    for (int o = 16; o; o >>= 1) s += __shfl_xor_sync(0xffffffffu, s, o);
    if (lane == 0) sh[wid] = s;
    __syncthreads();
    if (threadIdx.x == 0) {
        double S = 0.0;
        for (int w = 0; w < 8; w++) S += sh[w];
        float val = (float)(S / (double)BB);
        for (int k = 0; k < out_size; k++) out[k] = val;
    }
}

// ---------------- host launch ----------------
extern "C" void kernel_launch(void* const* d_in, const int* in_sizes, int n_in,
                              void* d_out, int out_size) {
    const int* pairs = (const int*)d_in[0];
    const int* ent_adj = (const int*)d_in[1];
    const int* rel_adj = (const int*)d_in[2];
    const int* adj_list = (const int*)d_in[3];
    const int* r_index = (const int*)d_in[4];
    const float* r_val = (const float*)d_in[5];
    const float* ent_emb = (const float*)d_in[7];
    const float* rel_emb = (const float*)d_in[8];
    const float* attn_e = (const float*)d_in[9];
    const float* attn_r = (const float*)d_in[10];
    float* out = (float*)d_out;

    const int NT = 256;
    const int gb_acc = (int)(((size_t)NN * DD + NT - 1) / NT);
    const int gb_ew = (int)(((size_t)TT * 32 + NT - 1) / NT);
    const int gb_et = (TT + NT - 1) / NT;

    k_zero<<<gb_acc, NT>>>();
    k_att_scatter<<<gb_ew, NT>>>(r_index + TT, r_val, rel_emb, attn_e, attn_r,
                                 ent_adj, ent_emb, rel_adj);
    k_zden<<<gb_et, NT>>>(adj_list);
    k_finalize_mean2<<<gb_acc, NT>>>();
    for (int l = 0; l < 2; l++) {
        k_reflect2<<<gb_ew, NT>>>(adj_list, l, r_index + TT, r_val, rel_emb);
        k_finalize_tanh2<<<gb_acc, NT>>>(l);
    }

    k_prep<<<BB + (NJ + 7) / 8, NT>>>(pairs);

    const int gemm_smem = 3 * 32768 + 1024;
    cudaFuncSetAttribute(k_gemm_tc, cudaFuncAttributeMaxDynamicSharedMemorySize, gemm_smem);
    dim3 gg(MR / 128, NJ / 128);
    k_gemm_tc<<<gg, 256, gemm_smem>>>();

    k_pass<<<MR, 256>>>();
    k_final<<<1, 256>>>(out, out_size);
}